// round 14
// baseline (speedup 1.0000x reference)
#include <cuda_runtime.h>
#include <cuda_bf16.h>
#include <mma.h>
#include <cstdint>

using namespace nvcuda;

#define NB 2
#define NS 2048
#define ND 768
#define NH 12
#define NDK 64
#define NM (NB*NS)
#define WSZ (ND*ND)

// ---- device-global scratch (allocation-free rule) ----
__device__ __nv_bfloat16 g_Qh[NM*ND], g_Ql[NM*ND];
__device__ __nv_bfloat16 g_Kh[NM*ND], g_Kl[NM*ND];
__device__ __nv_bfloat16 g_Vth[NM*ND], g_Vtl[NM*ND];   // [bh][d][s]
__device__ __nv_bfloat16 g_Ah[NM*ND], g_Al[NM*ND];     // split activations in
__device__ __nv_bfloat16 g_Xh[NM*ND], g_Xl[NM*ND];     // split attn out
__device__ __nv_bfloat16 g_Wh[4*WSZ], g_Wl[4*WSZ];     // split weights
__device__ float g_inv[NB*NH*NS];

// ---------------------------------------------------------------------------
__device__ __forceinline__ void split1(float x, __nv_bfloat16& h, __nv_bfloat16& l) {
  h = __float2bfloat16_rn(x);
  l = __float2bfloat16_rn(x - __bfloat162float(h));
}
__device__ __forceinline__ void split4(float4 v, __nv_bfloat16* hrow,
                                       __nv_bfloat16* lrow, int k) {
  __nv_bfloat16 h0,l0,h1,l1,h2,l2,h3,l3;
  split1(v.x,h0,l0); split1(v.y,h1,l1); split1(v.z,h2,l2); split1(v.w,h3,l3);
  *(__nv_bfloat162*)(hrow+k)   = __halves2bfloat162(h0,h1);
  *(__nv_bfloat162*)(hrow+k+2) = __halves2bfloat162(h2,h3);
  *(__nv_bfloat162*)(lrow+k)   = __halves2bfloat162(l0,l1);
  *(__nv_bfloat162*)(lrow+k+2) = __halves2bfloat162(l2,l3);
}

typedef wmma::fragment<wmma::matrix_a, 16,16,16, __nv_bfloat16, wmma::row_major> FragA;
typedef wmma::fragment<wmma::matrix_b, 16,16,16, __nv_bfloat16, wmma::col_major> FragB;
typedef wmma::fragment<wmma::accumulator, 16,16,16, float> FragC;

__device__ __forceinline__ void mma3(FragC& c, const FragA& ah, const FragA& al,
                                     const FragB& bh, const FragB& bl) {
  wmma::mma_sync(c, ah, bh, c);
  wmma::mma_sync(c, ah, bl, c);
  wmma::mma_sync(c, al, bh, c);
}

// raw m16n8k16 bf16 mma, fp32 accum
__device__ __forceinline__ void mma16816(float* c, const unsigned* a, unsigned b0, unsigned b1) {
  asm volatile(
    "mma.sync.aligned.m16n8k16.row.col.f32.bf16.bf16.f32 "
    "{%0,%1,%2,%3}, {%4,%5,%6,%7}, {%8,%9}, {%0,%1,%2,%3};\n"
    : "+f"(c[0]), "+f"(c[1]), "+f"(c[2]), "+f"(c[3])
    : "r"(a[0]), "r"(a[1]), "r"(a[2]), "r"(a[3]), "r"(b0), "r"(b1));
}

__device__ __forceinline__ void ldsm_x4(unsigned& r0, unsigned& r1,
                                        unsigned& r2, unsigned& r3, unsigned addr) {
  asm volatile("ldmatrix.sync.aligned.m8n8.x4.shared.b16 {%0,%1,%2,%3}, [%4];\n"
    : "=r"(r0), "=r"(r1), "=r"(r2), "=r"(r3) : "r"(addr));
}

__device__ __forceinline__ unsigned int smem_u32(const void* p) {
  return (unsigned int)__cvta_generic_to_shared(p);
}
__device__ __forceinline__ void cpa16(unsigned int dst, const void* src) {
  asm volatile("cp.async.cg.shared.global [%0], [%1], 16;\n" :: "r"(dst), "l"(src));
}
#define CP_COMMIT asm volatile("cp.async.commit_group;\n")
#define CP_WAIT0  asm volatile("cp.async.wait_group 0;\n")
#define CP_WAIT1  asm volatile("cp.async.wait_group 1;\n")

// ---------------------------------------------------------------------------
// split_kernel: fp32 -> bf16 hi/lo, elementwise (n % 4 == 0)
// ---------------------------------------------------------------------------
__global__ __launch_bounds__(256) void split_kernel(
    const float* __restrict__ in, __nv_bfloat16* __restrict__ h,
    __nv_bfloat16* __restrict__ l, int n)
{
  int i = (blockIdx.x*blockDim.x + threadIdx.x) << 2;
  if (i < n) {
    float4 v = *(const float4*)(in + i);
    split4(v, h, l, i);
  }
}

// ---------------------------------------------------------------------------
// linear_bf16: pre-split operands, cp.async double-buffer, 1 barrier/chunk.
// ---------------------------------------------------------------------------
#define LB_LD 40
#define LB_XB(buf,hl) ((buf)*30720 + (hl)*10240)
#define LB_WB(buf,hl) ((buf)*30720 + 20480 + (hl)*5120)
#define LB_CLD 68
#define LB_SMEM 61440

__global__ __launch_bounds__(256, 3) void linear_bf16_kernel(
    const __nv_bfloat16* __restrict__ Xh_g, const __nv_bfloat16* __restrict__ Xl_g,
    const __nv_bfloat16* __restrict__ Wh_g, const __nv_bfloat16* __restrict__ Wl_g,
    const float* __restrict__ bias, float* __restrict__ Out,
    __nv_bfloat16* __restrict__ OutH, __nv_bfloat16* __restrict__ OutL,
    int M, int N, int K, int mode)
{
  extern __shared__ char sm[];
  float* Cs = (float*)sm;

  const int m0 = blockIdx.y * 128;
  const int n0 = blockIdx.x * 64;
  const int t  = threadIdx.x;
  const int wid = t >> 5;
  const int wm  = wid >> 1;
  const int wn  = wid & 1;

  {
#pragma unroll
    for (int hl = 0; hl < 2; hl++) {
      const __nv_bfloat16* Xs = hl ? Xl_g : Xh_g;
      unsigned int xb = smem_u32(sm + LB_XB(0,hl));
#pragma unroll
      for (int i = 0; i < 2; i++) {
        int seg = t + 256*i;
        int r = seg >> 2, cs = seg & 3;
        cpa16(xb + r*80 + cs*16, Xs + (size_t)(m0 + r)*K + cs*8);
      }
      const __nv_bfloat16* Ws = hl ? Wl_g : Wh_g;
      unsigned int wb = smem_u32(sm + LB_WB(0,hl));
      {
        int r = t >> 2, cs = t & 3;
        cpa16(wb + r*80 + cs*16, Ws + (size_t)(n0 + r)*K + cs*8);
      }
    }
    CP_COMMIT;
  }

  FragC c[2][2];
#pragma unroll
  for (int i = 0; i < 2; i++)
#pragma unroll
    for (int j = 0; j < 2; j++) wmma::fill_fragment(c[i][j], 0.0f);

  const int NCH = K / 32;
  int buf = 0;
  for (int ch = 0; ch < NCH; ch++) {
    CP_WAIT0;
    __syncthreads();
    if (ch + 1 < NCH) {
      int k0 = (ch + 1) * 32;
      int nb = buf ^ 1;
#pragma unroll
      for (int hl = 0; hl < 2; hl++) {
        const __nv_bfloat16* Xs = hl ? Xl_g : Xh_g;
        unsigned int xb = smem_u32(sm + LB_XB(nb,hl));
#pragma unroll
        for (int i = 0; i < 2; i++) {
          int seg = t + 256*i;
          int r = seg >> 2, cs = seg & 3;
          cpa16(xb + r*80 + cs*16, Xs + (size_t)(m0 + r)*K + k0 + cs*8);
        }
        const __nv_bfloat16* Ws = hl ? Wl_g : Wh_g;
        unsigned int wb = smem_u32(sm + LB_WB(nb,hl));
        {
          int r = t >> 2, cs = t & 3;
          cpa16(wb + r*80 + cs*16, Ws + (size_t)(n0 + r)*K + k0 + cs*8);
        }
      }
      CP_COMMIT;
    }
    const __nv_bfloat16* Xh = (const __nv_bfloat16*)(sm + LB_XB(buf,0));
    const __nv_bfloat16* Xl = (const __nv_bfloat16*)(sm + LB_XB(buf,1));
    const __nv_bfloat16* Wh = (const __nv_bfloat16*)(sm + LB_WB(buf,0));
    const __nv_bfloat16* Wl = (const __nv_bfloat16*)(sm + LB_WB(buf,1));
#pragma unroll
    for (int ks = 0; ks < 32; ks += 16) {
      FragA ah[2], al[2];
      FragB bh[2], bl[2];
#pragma unroll
      for (int i = 0; i < 2; i++) {
        wmma::load_matrix_sync(ah[i], Xh + (wm*32 + i*16)*LB_LD + ks, LB_LD);
        wmma::load_matrix_sync(al[i], Xl + (wm*32 + i*16)*LB_LD + ks, LB_LD);
      }
#pragma unroll
      for (int j = 0; j < 2; j++) {
        wmma::load_matrix_sync(bh[j], Wh + (wn*32 + j*16)*LB_LD + ks, LB_LD);
        wmma::load_matrix_sync(bl[j], Wl + (wn*32 + j*16)*LB_LD + ks, LB_LD);
      }
#pragma unroll
      for (int i = 0; i < 2; i++)
#pragma unroll
        for (int j = 0; j < 2; j++) mma3(c[i][j], ah[i], al[i], bh[j], bl[j]);
    }
    buf ^= 1;
  }
  __syncthreads();
#pragma unroll
  for (int i = 0; i < 2; i++)
#pragma unroll
    for (int j = 0; j < 2; j++)
      wmma::store_matrix_sync(Cs + (wm*32 + i*16)*LB_CLD + wn*32 + j*16,
                              c[i][j], LB_CLD, wmma::mem_row_major);
  __syncthreads();

  if (mode == 0) {
    for (int i = t; i < 128*16; i += 256) {
      int row = i >> 4;
      int c4  = (i & 15) << 2;
      float4 v = *(const float4*)&Cs[row*LB_CLD + c4];
      float4 bb = *(const float4*)(bias + n0 + c4);
      v.x += bb.x; v.y += bb.y; v.z += bb.z; v.w += bb.w;
      *(float4*)&Out[(size_t)(m0 + row)*N + n0 + c4] = v;
    }
  } else if (mode == 1) {
    for (int i = t; i < 128*16; i += 256) {
      int row = i >> 4;
      int c4  = (i & 15) << 2;
      float4 v = *(const float4*)&Cs[row*LB_CLD + c4];
      float4 bb = *(const float4*)(bias + n0 + c4);
      v.x += bb.x; v.y += bb.y; v.z += bb.z; v.w += bb.w;
      size_t base = (size_t)(m0 + row)*N + n0 + c4;
      split4(v, OutH + base, OutL + base, 0);
    }
  } else {
    for (int j = t; j < 64*128; j += 256) {
      int d   = j >> 7;
      int row = j & 127;
      float val = Cs[row*LB_CLD + d] + bias[n0 + d];
      __nv_bfloat16 h, l;
      split1(val, h, l);
      int m  = m0 + row;
      int bb = m >> 11;
      int s  = m & 2047;
      int n  = n0 + d;
      int hh = n >> 6;
      int dd = n & 63;
      size_t idx = ((size_t)(bb*NH + hh)*NDK + dd)*NS + s;
      OutH[idx] = h;
      OutL[idx] = l;
    }
  }
}

// ---------------------------------------------------------------------------
// Scores (raw mma + ldmatrix.x4): CTA = 64 q x 2048 keys; chunk = 64 keys.
// Triple-buffered cp.async K ring, register epilogue, LDSM fragment loads.
// ---------------------------------------------------------------------------
#define SLD 72
#define S_QHO 0
#define S_QLO 9216
#define S_KB(buf,hl) (18432 + ((buf)*2 + (hl))*9216)
#define S_SUMO 73728
#define S_SMEM 73984

__global__ __launch_bounds__(256, 3) void scores_kernel(
    const __nv_bfloat16* __restrict__ Qh_g, const __nv_bfloat16* __restrict__ Ql_g,
    const __nv_bfloat16* __restrict__ Kh_g, const __nv_bfloat16* __restrict__ Kl_g,
    float* __restrict__ attn_out, float* __restrict__ inv_out)
{
  extern __shared__ char sm[];
  float* ssum = (float*)(sm + S_SUMO);

  const int t  = threadIdx.x;
  const int q0 = blockIdx.x * 64;
  const int bh = blockIdx.y;
  const int b  = bh / NH, h = bh % NH;
  const int wid = t >> 5;
  const int lane = t & 31;
  const int g  = lane >> 2;
  const int tq = lane & 3;
  const int wq = (wid >> 1) * 16;
  const int wk = (wid & 1) * 32;

  // ldmatrix lane addressing
  const int sub = lane >> 3, l7 = lane & 7;
  // A tiles: rows wq + (sub&1)*8 + l7 ; cols (sub>>1)*8
  const unsigned qh_addr0 = smem_u32(sm + S_QHO) +
      (unsigned)(((wq + (sub & 1)*8 + l7)*SLD + (sub >> 1)*8) * 2);
  const unsigned ql_addr0 = qh_addr0 + (S_QLO - S_QHO);
  // B tiles (keys): rows wk + (sub>>1)*8 + l7 ; cols (sub&1)*8
  const unsigned k_off0 = (unsigned)(((wk + (sub >> 1)*8 + l7)*SLD + (sub & 1)*8) * 2);
  const unsigned k_off1 = k_off0 + 16*SLD*2;

  const size_t qkoff = ((size_t)b*NS)*ND + h*NDK;
  float* Arows = attn_out + ((size_t)bh*NS + q0)*NS;

  if (t < 64) ssum[t] = 0.f;

  {
    unsigned int qh = smem_u32(sm + S_QHO), ql = smem_u32(sm + S_QLO);
#pragma unroll
    for (int i = 0; i < 2; i++) {
      int f = t + 256*i;
      int r = f >> 3;
      int c = (f & 7) * 8;
      cpa16(qh + r*144 + c*2, Qh_g + qkoff + (size_t)(q0 + r)*ND + c);
      cpa16(ql + r*144 + c*2, Ql_g + qkoff + (size_t)(q0 + r)*ND + c);
    }
    unsigned int kh = smem_u32(sm + S_KB(0,0)), kl = smem_u32(sm + S_KB(0,1));
#pragma unroll
    for (int i = 0; i < 2; i++) {
      int f = t + 256*i;
      int r = f >> 3;
      int c = (f & 7) * 8;
      cpa16(kh + r*144 + c*2, Kh_g + qkoff + (size_t)r*ND + c);
      cpa16(kl + r*144 + c*2, Kl_g + qkoff + (size_t)r*ND + c);
    }
    CP_COMMIT;
  }

  int rbuf = 0;
  for (int ch = 0; ch < 32; ch++) {
    if (ch < 31) {
      int kt = (ch + 1) * 64;
      int wbuf = rbuf + 1; if (wbuf == 3) wbuf = 0;
      unsigned int kh = smem_u32(sm + S_KB(wbuf,0)), kl = smem_u32(sm + S_KB(wbuf,1));
#pragma unroll
      for (int i = 0; i < 2; i++) {
        int f = t + 256*i;
        int r = f >> 3;
        int c = (f & 7) * 8;
        cpa16(kh + r*144 + c*2, Kh_g + qkoff + (size_t)(kt + r)*ND + c);
        cpa16(kl + r*144 + c*2, Kl_g + qkoff + (size_t)(kt + r)*ND + c);
      }
      CP_COMMIT;
      CP_WAIT1;
    } else {
      CP_WAIT0;
    }
    __syncthreads();

    const unsigned kh_base = smem_u32(sm + S_KB(rbuf, 0));
    const unsigned kl_base = kh_base + 9216;

    float c[4][4];
#pragma unroll
    for (int nt = 0; nt < 4; nt++)
#pragma unroll
      for (int j = 0; j < 4; j++) c[nt][j] = 0.f;

#pragma unroll
    for (int ks = 0; ks < 64; ks += 16) {
      unsigned ah[4], al[4];
      ldsm_x4(ah[0], ah[1], ah[2], ah[3], qh_addr0 + ks*2);
      ldsm_x4(al[0], al[1], al[2], al[3], ql_addr0 + ks*2);
      unsigned bh00, bh01, bh10, bh11;   // b0h(nt0), b1h(nt0), b0h(nt1), b1h(nt1)
      unsigned bh20, bh21, bh30, bh31;
      unsigned bl00, bl01, bl10, bl11;
      unsigned bl20, bl21, bl30, bl31;
      ldsm_x4(bh00, bh01, bh10, bh11, kh_base + k_off0 + ks*2);
      ldsm_x4(bh20, bh21, bh30, bh31, kh_base + k_off1 + ks*2);
      ldsm_x4(bl00, bl01, bl10, bl11, kl_base + k_off0 + ks*2);
      ldsm_x4(bl20, bl21, bl30, bl31, kl_base + k_off1 + ks*2);
      mma16816(c[0], ah, bh00, bh01);
      mma16816(c[0], ah, bl00, bl01);
      mma16816(c[0], al, bh00, bh01);
      mma16816(c[1], ah, bh10, bh11);
      mma16816(c[1], ah, bl10, bl11);
      mma16816(c[1], al, bh10, bh11);
      mma16816(c[2], ah, bh20, bh21);
      mma16816(c[2], ah, bl20, bl21);
      mma16816(c[2], al, bh20, bh21);
      mma16816(c[3], ah, bh30, bh31);
      mma16816(c[3], ah, bl30, bl31);
      mma16816(c[3], al, bh30, bh31);
    }

    float s0 = 0.f, s1 = 0.f;
    const int r0 = wq + g, r1 = wq + g + 8;
#pragma unroll
    for (int nt = 0; nt < 4; nt++) {
      int gcol = ch*64 + wk + nt*8 + tq*2;
      float e0 = __expf(c[nt][0] * 0.125f);
      float e1 = __expf(c[nt][1] * 0.125f);
      float e2 = __expf(c[nt][2] * 0.125f);
      float e3 = __expf(c[nt][3] * 0.125f);
      s0 += e0 + e1;
      s1 += e2 + e3;
      float2 p0; p0.x = e0; p0.y = e1;
      float2 p1; p1.x = e2; p1.y = e3;
      *(float2*)&Arows[(size_t)r0*NS + gcol] = p0;
      *(float2*)&Arows[(size_t)r1*NS + gcol] = p1;
    }
    s0 += __shfl_xor_sync(0xffffffffu, s0, 1);
    s0 += __shfl_xor_sync(0xffffffffu, s0, 2);
    s1 += __shfl_xor_sync(0xffffffffu, s1, 1);
    s1 += __shfl_xor_sync(0xffffffffu, s1, 2);
    if (tq == 0) {
      atomicAdd(&ssum[r0], s0);
      atomicAdd(&ssum[r1], s1);
    }
    rbuf = rbuf + 1; if (rbuf == 3) rbuf = 0;
  }
  __syncthreads();
  if (t < 64) inv_out[(size_t)bh*NS + q0 + t] = 1.0f / ssum[t];
}

// ---------------------------------------------------------------------------
// PV: CTA = 64 q x 64 d; L2-prefetch of next P chunk hides the cold-DRAM LDG.
// Epilogue writes SPLIT bf16 X for the final linear.
// ---------------------------------------------------------------------------
#define SCLD 68
#define P_PHO 0
#define P_PLO 9216
#define P_VB(buf,hl) (18432 + ((buf)*2 + (hl))*9216)
#define P_CSO 0
#define P_INVO 55296
#define P_SMEM 55552

__global__ __launch_bounds__(256, 3) void pv_kernel(
    float* __restrict__ attn, const __nv_bfloat16* __restrict__ Vth_g,
    const __nv_bfloat16* __restrict__ Vtl_g,
    const float* __restrict__ inv_in,
    __nv_bfloat16* __restrict__ XhG, __nv_bfloat16* __restrict__ XlG)
{
  extern __shared__ char sm[];
  __nv_bfloat16* Ph = (__nv_bfloat16*)(sm + P_PHO);
  __nv_bfloat16* Pl = (__nv_bfloat16*)(sm + P_PLO);
  float* sinv = (float*)(sm + P_INVO);
  float* Cs   = (float*)(sm + P_CSO);

  const int t  = threadIdx.x;
  const int q0 = blockIdx.x * 64;
  const int bh = blockIdx.y;
  const int b  = bh / NH, h = bh % NH;
  const int wid = t >> 5;
  const int wq  = (wid >> 1) * 16;
  const int wd  = (wid & 1) * 32;

  float* Arows = attn + ((size_t)bh*NS + q0)*NS;
  const size_t voff = (size_t)bh*NDK*NS;

  if (t < 64) sinv[t] = inv_in[(size_t)bh*NS + q0 + t];

  {
    unsigned int vh = smem_u32(sm + P_VB(0,0)), vl = smem_u32(sm + P_VB(0,1));
#pragma unroll
    for (int i = 0; i < 2; i++) {
      int f = t + 256*i;
      int r = f >> 3;
      int c = (f & 7) * 8;
      cpa16(vh + r*144 + c*2, Vth_g + voff + (size_t)r*NS + c);
      cpa16(vl + r*144 + c*2, Vtl_g + voff + (size_t)r*NS + c);
    }
    CP_COMMIT;
  }
  // prefetch P chunk 0 into L2
  {
    int row = t >> 2;
    int cb  = (t & 3) * 16;
    asm volatile("prefetch.global.L2 [%0];" :: "l"(Arows + (size_t)row*NS + cb));
  }
  __syncthreads();

  FragC c0, c1;
  wmma::fill_fragment(c0, 0.0f);
  wmma::fill_fragment(c1, 0.0f);

  for (int ch = 0; ch < 32; ch++) {
    if (ch < 31) {
      int kt = (ch + 1) * 64;
      int buf = (ch + 1) & 1;
      unsigned int vh = smem_u32(sm + P_VB(buf,0)), vl = smem_u32(sm + P_VB(buf,1));
#pragma unroll
      for (int i = 0; i < 2; i++) {
        int f = t + 256*i;
        int r = f >> 3;
        int c = (f & 7) * 8;
        cpa16(vh + r*144 + c*2, Vth_g + voff + (size_t)r*NS + kt + c);
        cpa16(vl + r*144 + c*2, Vtl_g + voff + (size_t)r*NS + kt + c);
      }
      CP_COMMIT;
    }
    {
      int row = t >> 2;
      int cb  = (t & 3) * 16;
      float inv = sinv[row];
      float* ap = Arows + (size_t)row*NS + ch*64 + cb;
      if (ch < 31)   // L2-prefetch next chunk's P lines
        asm volatile("prefetch.global.L2 [%0];" :: "l"(ap + 64));
#pragma unroll
      for (int i = 0; i < 4; i++) {
        float4 p = *(const float4*)(ap + 4*i);
        p.x *= inv; p.y *= inv; p.z *= inv; p.w *= inv;
        *(float4*)(ap + 4*i) = p;
        split4(p, Ph + row*SLD, Pl + row*SLD, cb + 4*i);
      }
    }
    if (ch < 31) { CP_WAIT1; } else { CP_WAIT0; }
    __syncthreads();

    const __nv_bfloat16* Vbh = (const __nv_bfloat16*)(sm + P_VB(ch & 1, 0));
    const __nv_bfloat16* Vbl = (const __nv_bfloat16*)(sm + P_VB(ch & 1, 1));
#pragma unroll
    for (int ks = 0; ks < 64; ks += 16) {
      FragA ah, al;
      FragB b0h, b0l, b1h, b1l;
      wmma::load_matrix_sync(ah, Ph + wq*SLD + ks, SLD);
      wmma::load_matrix_sync(al, Pl + wq*SLD + ks, SLD);
      wmma::load_matrix_sync(b0h, Vbh + (wd+ 0)*SLD + ks, SLD);
      wmma::load_matrix_sync(b0l, Vbl + (wd+ 0)*SLD + ks, SLD);
      wmma::load_matrix_sync(b1h, Vbh + (wd+16)*SLD + ks, SLD);
      wmma::load_matrix_sync(b1l, Vbl + (wd+16)*SLD + ks, SLD);
      mma3(c0, ah, al, b0h, b0l);
      mma3(c1, ah, al, b1h, b1l);
    }
    __syncthreads();
  }

  wmma::store_matrix_sync(Cs + wq*SCLD + wd,      c0, SCLD, wmma::mem_row_major);
  wmma::store_matrix_sync(Cs + wq*SCLD + wd + 16, c1, SCLD, wmma::mem_row_major);
  __syncthreads();
  for (int i = t; i < 64*16; i += 256) {
    int row = i >> 4;
    int d4  = (i & 15) << 2;
    float4 v = *(const float4*)&Cs[row*SCLD + d4];
    size_t base = (size_t)(b*NS + q0 + row)*ND + h*NDK + d4;
    split4(v, XhG + base, XlG + base, 0);
  }
}

// ---------------------------------------------------------------------------
extern "C" void kernel_launch(void* const* d_in, const int* in_sizes, int n_in,
                              void* d_out, int out_size)
{
  const float* q   = (const float*)d_in[0];
  const float* k   = (const float*)d_in[1];
  const float* v   = (const float*)d_in[2];
  const float* w_q = (const float*)d_in[3];
  const float* b_q = (const float*)d_in[4];
  const float* w_k = (const float*)d_in[5];
  const float* b_k = (const float*)d_in[6];
  const float* w_v = (const float*)d_in[7];
  const float* b_v = (const float*)d_in[8];
  const float* w_o = (const float*)d_in[9];
  const float* b_o = (const float*)d_in[10];

  __nv_bfloat16 *qh, *ql, *kh, *kl, *vth, *vtl, *ah, *al, *xh, *xl, *wh, *wl;
  float *ginv;
  cudaGetSymbolAddress((void**)&qh,  g_Qh);
  cudaGetSymbolAddress((void**)&ql,  g_Ql);
  cudaGetSymbolAddress((void**)&kh,  g_Kh);
  cudaGetSymbolAddress((void**)&kl,  g_Kl);
  cudaGetSymbolAddress((void**)&vth, g_Vth);
  cudaGetSymbolAddress((void**)&vtl, g_Vtl);
  cudaGetSymbolAddress((void**)&ah,  g_Ah);
  cudaGetSymbolAddress((void**)&al,  g_Al);
  cudaGetSymbolAddress((void**)&xh,  g_Xh);
  cudaGetSymbolAddress((void**)&xl,  g_Xl);
  cudaGetSymbolAddress((void**)&wh,  g_Wh);
  cudaGetSymbolAddress((void**)&wl,  g_Wl);
  cudaGetSymbolAddress((void**)&ginv, g_inv);

  const size_t OUT_E = (size_t)NB * NS * ND;
  float* outp  = (float*)d_out;
  float* attnp = outp + OUT_E;

  cudaFuncSetAttribute(linear_bf16_kernel, cudaFuncAttributeMaxDynamicSharedMemorySize, LB_SMEM);
  cudaFuncSetAttribute(scores_kernel,      cudaFuncAttributeMaxDynamicSharedMemorySize, S_SMEM);
  cudaFuncSetAttribute(pv_kernel,          cudaFuncAttributeMaxDynamicSharedMemorySize, P_SMEM);

  const int NACT = NM*ND;
  const int GACT = (NACT/4 + 255)/256;
  const int GW   = (WSZ/4 + 255)/256;

  split_kernel<<<GW, 256>>>(w_q, wh + 0*WSZ, wl + 0*WSZ, WSZ);
  split_kernel<<<GW, 256>>>(w_k, wh + 1*WSZ, wl + 1*WSZ, WSZ);
  split_kernel<<<GW, 256>>>(w_v, wh + 2*WSZ, wl + 2*WSZ, WSZ);
  split_kernel<<<GW, 256>>>(w_o, wh + 3*WSZ, wl + 3*WSZ, WSZ);

  dim3 gproj(ND/64, NM/128);   // (12, 32)
  split_kernel<<<GACT, 256>>>(q, ah, al, NACT);
  linear_bf16_kernel<<<gproj, 256, LB_SMEM>>>(ah, al, wh + 0*WSZ, wl + 0*WSZ,
                                              b_q, nullptr, qh, ql, NM, ND, ND, 1);
  split_kernel<<<GACT, 256>>>(k, ah, al, NACT);
  linear_bf16_kernel<<<gproj, 256, LB_SMEM>>>(ah, al, wh + 1*WSZ, wl + 1*WSZ,
                                              b_k, nullptr, kh, kl, NM, ND, ND, 1);
  split_kernel<<<GACT, 256>>>(v, ah, al, NACT);
  linear_bf16_kernel<<<gproj, 256, LB_SMEM>>>(ah, al, wh + 2*WSZ, wl + 2*WSZ,
                                              b_v, nullptr, vth, vtl, NM, ND, ND, 2);

  dim3 gattn(NS/64, NB*NH);    // (32, 24)
  scores_kernel<<<gattn, 256, S_SMEM>>>(qh, ql, kh, kl, attnp, ginv);
  pv_kernel<<<gattn, 256, P_SMEM>>>(attnp, vth, vtl, ginv, xh, xl);

  linear_bf16_kernel<<<gproj, 256, LB_SMEM>>>(xh, xl, wh + 3*WSZ, wl + 3*WSZ,
                                              b_o, outp, nullptr, nullptr, NM, ND, ND, 0);
}

// round 15
// speedup vs baseline: 1.0188x; 1.0188x over previous
#include <cuda_runtime.h>
#include <cuda_bf16.h>
#include <mma.h>
#include <cstdint>

using namespace nvcuda;

#define NB 2
#define NS 2048
#define ND 768
#define NH 12
#define NDK 64
#define NM (NB*NS)
#define WSZ (ND*ND)

// ---- device-global scratch (allocation-free rule) ----
__device__ __nv_bfloat16 g_Qh[NM*ND], g_Ql[NM*ND];
__device__ __nv_bfloat16 g_Kh[NM*ND], g_Kl[NM*ND];
__device__ __nv_bfloat16 g_Vth[NM*ND], g_Vtl[NM*ND];   // [bh][d][s]
__device__ __nv_bfloat16 g_Ah[NM*ND], g_Al[NM*ND];     // split activations in
__device__ __nv_bfloat16 g_Xh[NM*ND], g_Xl[NM*ND];     // split attn out
__device__ __nv_bfloat16 g_Wh[4*WSZ], g_Wl[4*WSZ];     // split weights

// ---------------------------------------------------------------------------
__device__ __forceinline__ void split1(float x, __nv_bfloat16& h, __nv_bfloat16& l) {
  h = __float2bfloat16_rn(x);
  l = __float2bfloat16_rn(x - __bfloat162float(h));
}
__device__ __forceinline__ void split4(float4 v, __nv_bfloat16* hrow,
                                       __nv_bfloat16* lrow, int k) {
  __nv_bfloat16 h0,l0,h1,l1,h2,l2,h3,l3;
  split1(v.x,h0,l0); split1(v.y,h1,l1); split1(v.z,h2,l2); split1(v.w,h3,l3);
  *(__nv_bfloat162*)(hrow+k)   = __halves2bfloat162(h0,h1);
  *(__nv_bfloat162*)(hrow+k+2) = __halves2bfloat162(h2,h3);
  *(__nv_bfloat162*)(lrow+k)   = __halves2bfloat162(l0,l1);
  *(__nv_bfloat162*)(lrow+k+2) = __halves2bfloat162(l2,l3);
}
// pack two floats -> bf16x2 (hi) and residual bf16x2 (lo)
__device__ __forceinline__ void pack_hilo(float a, float b, unsigned& hi, unsigned& lo) {
  __nv_bfloat16 ha = __float2bfloat16_rn(a);
  __nv_bfloat16 hb = __float2bfloat16_rn(b);
  __nv_bfloat16 la = __float2bfloat16_rn(a - __bfloat162float(ha));
  __nv_bfloat16 lb = __float2bfloat16_rn(b - __bfloat162float(hb));
  __nv_bfloat162 th = __halves2bfloat162(ha, hb);
  __nv_bfloat162 tl = __halves2bfloat162(la, lb);
  hi = *(unsigned*)&th;
  lo = *(unsigned*)&tl;
}

typedef wmma::fragment<wmma::matrix_a, 16,16,16, __nv_bfloat16, wmma::row_major> FragA;
typedef wmma::fragment<wmma::matrix_b, 16,16,16, __nv_bfloat16, wmma::col_major> FragB;
typedef wmma::fragment<wmma::accumulator, 16,16,16, float> FragC;

__device__ __forceinline__ void mma3(FragC& c, const FragA& ah, const FragA& al,
                                     const FragB& bh, const FragB& bl) {
  wmma::mma_sync(c, ah, bh, c);
  wmma::mma_sync(c, ah, bl, c);
  wmma::mma_sync(c, al, bh, c);
}

// raw m16n8k16 bf16 mma, fp32 accum
__device__ __forceinline__ void mma16816(float* c, const unsigned* a, unsigned b0, unsigned b1) {
  asm volatile(
    "mma.sync.aligned.m16n8k16.row.col.f32.bf16.bf16.f32 "
    "{%0,%1,%2,%3}, {%4,%5,%6,%7}, {%8,%9}, {%0,%1,%2,%3};\n"
    : "+f"(c[0]), "+f"(c[1]), "+f"(c[2]), "+f"(c[3])
    : "r"(a[0]), "r"(a[1]), "r"(a[2]), "r"(a[3]), "r"(b0), "r"(b1));
}

__device__ __forceinline__ void ldsm_x4(unsigned& r0, unsigned& r1,
                                        unsigned& r2, unsigned& r3, unsigned addr) {
  asm volatile("ldmatrix.sync.aligned.m8n8.x4.shared.b16 {%0,%1,%2,%3}, [%4];\n"
    : "=r"(r0), "=r"(r1), "=r"(r2), "=r"(r3) : "r"(addr));
}

__device__ __forceinline__ unsigned int smem_u32(const void* p) {
  return (unsigned int)__cvta_generic_to_shared(p);
}
__device__ __forceinline__ void cpa16(unsigned int dst, const void* src) {
  asm volatile("cp.async.cg.shared.global [%0], [%1], 16;\n" :: "r"(dst), "l"(src));
}
#define CP_COMMIT asm volatile("cp.async.commit_group;\n")
#define CP_WAIT0  asm volatile("cp.async.wait_group 0;\n")
#define CP_WAIT1  asm volatile("cp.async.wait_group 1;\n")

// ---------------------------------------------------------------------------
// split_kernel: fp32 -> bf16 hi/lo, elementwise (n % 4 == 0)
// ---------------------------------------------------------------------------
__global__ __launch_bounds__(256) void split_kernel(
    const float* __restrict__ in, __nv_bfloat16* __restrict__ h,
    __nv_bfloat16* __restrict__ l, int n)
{
  int i = (blockIdx.x*blockDim.x + threadIdx.x) << 2;
  if (i < n) {
    float4 v = *(const float4*)(in + i);
    split4(v, h, l, i);
  }
}

// ---------------------------------------------------------------------------
// linear_bf16: pre-split operands, cp.async double-buffer, 1 barrier/chunk.
// ---------------------------------------------------------------------------
#define LB_LD 40
#define LB_XB(buf,hl) ((buf)*30720 + (hl)*10240)
#define LB_WB(buf,hl) ((buf)*30720 + 20480 + (hl)*5120)
#define LB_CLD 68
#define LB_SMEM 61440

__global__ __launch_bounds__(256, 3) void linear_bf16_kernel(
    const __nv_bfloat16* __restrict__ Xh_g, const __nv_bfloat16* __restrict__ Xl_g,
    const __nv_bfloat16* __restrict__ Wh_g, const __nv_bfloat16* __restrict__ Wl_g,
    const float* __restrict__ bias, float* __restrict__ Out,
    __nv_bfloat16* __restrict__ OutH, __nv_bfloat16* __restrict__ OutL,
    int M, int N, int K, int mode)
{
  extern __shared__ char sm[];
  float* Cs = (float*)sm;

  const int m0 = blockIdx.y * 128;
  const int n0 = blockIdx.x * 64;
  const int t  = threadIdx.x;
  const int wid = t >> 5;
  const int wm  = wid >> 1;
  const int wn  = wid & 1;

  {
#pragma unroll
    for (int hl = 0; hl < 2; hl++) {
      const __nv_bfloat16* Xs = hl ? Xl_g : Xh_g;
      unsigned int xb = smem_u32(sm + LB_XB(0,hl));
#pragma unroll
      for (int i = 0; i < 2; i++) {
        int seg = t + 256*i;
        int r = seg >> 2, cs = seg & 3;
        cpa16(xb + r*80 + cs*16, Xs + (size_t)(m0 + r)*K + cs*8);
      }
      const __nv_bfloat16* Ws = hl ? Wl_g : Wh_g;
      unsigned int wb = smem_u32(sm + LB_WB(0,hl));
      {
        int r = t >> 2, cs = t & 3;
        cpa16(wb + r*80 + cs*16, Ws + (size_t)(n0 + r)*K + cs*8);
      }
    }
    CP_COMMIT;
  }

  FragC c[2][2];
#pragma unroll
  for (int i = 0; i < 2; i++)
#pragma unroll
    for (int j = 0; j < 2; j++) wmma::fill_fragment(c[i][j], 0.0f);

  const int NCH = K / 32;
  int buf = 0;
  for (int ch = 0; ch < NCH; ch++) {
    CP_WAIT0;
    __syncthreads();
    if (ch + 1 < NCH) {
      int k0 = (ch + 1) * 32;
      int nb = buf ^ 1;
#pragma unroll
      for (int hl = 0; hl < 2; hl++) {
        const __nv_bfloat16* Xs = hl ? Xl_g : Xh_g;
        unsigned int xb = smem_u32(sm + LB_XB(nb,hl));
#pragma unroll
        for (int i = 0; i < 2; i++) {
          int seg = t + 256*i;
          int r = seg >> 2, cs = seg & 3;
          cpa16(xb + r*80 + cs*16, Xs + (size_t)(m0 + r)*K + k0 + cs*8);
        }
        const __nv_bfloat16* Ws = hl ? Wl_g : Wh_g;
        unsigned int wb = smem_u32(sm + LB_WB(nb,hl));
        {
          int r = t >> 2, cs = t & 3;
          cpa16(wb + r*80 + cs*16, Ws + (size_t)(n0 + r)*K + k0 + cs*8);
        }
      }
      CP_COMMIT;
    }
    const __nv_bfloat16* Xh = (const __nv_bfloat16*)(sm + LB_XB(buf,0));
    const __nv_bfloat16* Xl = (const __nv_bfloat16*)(sm + LB_XB(buf,1));
    const __nv_bfloat16* Wh = (const __nv_bfloat16*)(sm + LB_WB(buf,0));
    const __nv_bfloat16* Wl = (const __nv_bfloat16*)(sm + LB_WB(buf,1));
#pragma unroll
    for (int ks = 0; ks < 32; ks += 16) {
      FragA ah[2], al[2];
      FragB bh[2], bl[2];
#pragma unroll
      for (int i = 0; i < 2; i++) {
        wmma::load_matrix_sync(ah[i], Xh + (wm*32 + i*16)*LB_LD + ks, LB_LD);
        wmma::load_matrix_sync(al[i], Xl + (wm*32 + i*16)*LB_LD + ks, LB_LD);
      }
#pragma unroll
      for (int j = 0; j < 2; j++) {
        wmma::load_matrix_sync(bh[j], Wh + (wn*32 + j*16)*LB_LD + ks, LB_LD);
        wmma::load_matrix_sync(bl[j], Wl + (wn*32 + j*16)*LB_LD + ks, LB_LD);
      }
#pragma unroll
      for (int i = 0; i < 2; i++)
#pragma unroll
        for (int j = 0; j < 2; j++) mma3(c[i][j], ah[i], al[i], bh[j], bl[j]);
    }
    buf ^= 1;
  }
  __syncthreads();
#pragma unroll
  for (int i = 0; i < 2; i++)
#pragma unroll
    for (int j = 0; j < 2; j++)
      wmma::store_matrix_sync(Cs + (wm*32 + i*16)*LB_CLD + wn*32 + j*16,
                              c[i][j], LB_CLD, wmma::mem_row_major);
  __syncthreads();

  if (mode == 0) {
    for (int i = t; i < 128*16; i += 256) {
      int row = i >> 4;
      int c4  = (i & 15) << 2;
      float4 v = *(const float4*)&Cs[row*LB_CLD + c4];
      float4 bb = *(const float4*)(bias + n0 + c4);
      v.x += bb.x; v.y += bb.y; v.z += bb.z; v.w += bb.w;
      *(float4*)&Out[(size_t)(m0 + row)*N + n0 + c4] = v;
    }
  } else if (mode == 1) {
    for (int i = t; i < 128*16; i += 256) {
      int row = i >> 4;
      int c4  = (i & 15) << 2;
      float4 v = *(const float4*)&Cs[row*LB_CLD + c4];
      float4 bb = *(const float4*)(bias + n0 + c4);
      v.x += bb.x; v.y += bb.y; v.z += bb.z; v.w += bb.w;
      size_t base = (size_t)(m0 + row)*N + n0 + c4;
      split4(v, OutH + base, OutL + base, 0);
    }
  } else {
    for (int j = t; j < 64*128; j += 256) {
      int d   = j >> 7;
      int row = j & 127;
      float val = Cs[row*LB_CLD + d] + bias[n0 + d];
      __nv_bfloat16 h, l;
      split1(val, h, l);
      int m  = m0 + row;
      int bb = m >> 11;
      int s  = m & 2047;
      int n  = n0 + d;
      int hh = n >> 6;
      int dd = n & 63;
      size_t idx = ((size_t)(bb*NH + hh)*NDK + dd)*NS + s;
      OutH[idx] = h;
      OutL[idx] = l;
    }
  }
}

// ---------------------------------------------------------------------------
// Fused attention: CTA = 64 q x one (b,h), chunks of 64 keys.
// Per chunk: QK mma (LDSM) -> exp in regs -> STG unnorm P + row sums ->
// PV mma DIRECTLY from registers (exp packed to bf16 hi/lo A-frags) against
// double-buffered V. Tail: cross-warp pair reduction, scale by 1/sum, write
// split X; then in-kernel normalize sweep over the CTA's own P strip.
// ---------------------------------------------------------------------------
#define FLD 72
#define F_QHO 0
#define F_QLO 9216
#define F_KB(buf,hl) (18432 + (buf)*18432 + (hl)*9216)
#define F_VB(buf,hl) (55296 + (buf)*18432 + (hl)*9216)
#define F_SUMO 92160
#define F_INVO 92416
#define F_SCR  18432              // reduction scratch aliases K ring
#define F_SMEM 92672

__global__ __launch_bounds__(256, 2) void attn_fused_kernel(
    const __nv_bfloat16* __restrict__ Qh_g, const __nv_bfloat16* __restrict__ Ql_g,
    const __nv_bfloat16* __restrict__ Kh_g, const __nv_bfloat16* __restrict__ Kl_g,
    const __nv_bfloat16* __restrict__ Vth_g, const __nv_bfloat16* __restrict__ Vtl_g,
    float* __restrict__ attn_out,
    __nv_bfloat16* __restrict__ XhG, __nv_bfloat16* __restrict__ XlG)
{
  extern __shared__ char sm[];
  float* ssum = (float*)(sm + F_SUMO);
  float* sinv = (float*)(sm + F_INVO);

  const int t  = threadIdx.x;
  const int q0 = blockIdx.x * 64;
  const int bh = blockIdx.y;
  const int b  = bh / NH, h = bh % NH;
  const int wid = t >> 5;
  const int lane = t & 31;
  const int g  = lane >> 2;
  const int tq = lane & 3;
  const int wq = (wid >> 1) * 16;
  const int wk = (wid & 1) * 32;

  // ldmatrix lane addressing (Q rows / K keys)
  const int sub = lane >> 3, l7 = lane & 7;
  const unsigned qh_addr0 = smem_u32(sm + F_QHO) +
      (unsigned)(((wq + (sub & 1)*8 + l7)*FLD + (sub >> 1)*8) * 2);
  const unsigned ql_addr0 = qh_addr0 + (F_QLO - F_QHO);
  const unsigned k_off0 = (unsigned)(((wk + (sub >> 1)*8 + l7)*FLD + (sub & 1)*8) * 2);
  const unsigned k_off1 = k_off0 + 16*FLD*2;

  const size_t qkoff = ((size_t)b*NS)*ND + h*NDK;
  const size_t voff  = (size_t)bh*NDK*NS;
  float* Arows = attn_out + ((size_t)bh*NS + q0)*NS;

  if (t < 64) ssum[t] = 0.f;

  // preload Q + K chunk0 + V chunk0
  {
    unsigned int qh = smem_u32(sm + F_QHO), ql = smem_u32(sm + F_QLO);
#pragma unroll
    for (int i = 0; i < 2; i++) {
      int f = t + 256*i;
      int r = f >> 3;
      int c = (f & 7) * 8;
      cpa16(qh + r*144 + c*2, Qh_g + qkoff + (size_t)(q0 + r)*ND + c);
      cpa16(ql + r*144 + c*2, Ql_g + qkoff + (size_t)(q0 + r)*ND + c);
    }
    unsigned int kh = smem_u32(sm + F_KB(0,0)), kl = smem_u32(sm + F_KB(0,1));
    unsigned int vh = smem_u32(sm + F_VB(0,0)), vl = smem_u32(sm + F_VB(0,1));
#pragma unroll
    for (int i = 0; i < 2; i++) {
      int f = t + 256*i;
      int r = f >> 3;
      int c = (f & 7) * 8;
      cpa16(kh + r*144 + c*2, Kh_g + qkoff + (size_t)r*ND + c);
      cpa16(kl + r*144 + c*2, Kl_g + qkoff + (size_t)r*ND + c);
      cpa16(vh + r*144 + c*2, Vth_g + voff + (size_t)r*NS + c);
      cpa16(vl + r*144 + c*2, Vtl_g + voff + (size_t)r*NS + c);
    }
    CP_COMMIT;
  }

  float o[8][4];
#pragma unroll
  for (int dt = 0; dt < 8; dt++)
#pragma unroll
    for (int j = 0; j < 4; j++) o[dt][j] = 0.f;

  int buf = 0;
  for (int ch = 0; ch < 32; ch++) {
    if (ch < 31) {
      int kt = (ch + 1) * 64;
      int nb = buf ^ 1;
      unsigned int kh = smem_u32(sm + F_KB(nb,0)), kl = smem_u32(sm + F_KB(nb,1));
      unsigned int vh = smem_u32(sm + F_VB(nb,0)), vl = smem_u32(sm + F_VB(nb,1));
#pragma unroll
      for (int i = 0; i < 2; i++) {
        int f = t + 256*i;
        int r = f >> 3;
        int c = (f & 7) * 8;
        cpa16(kh + r*144 + c*2, Kh_g + qkoff + (size_t)(kt + r)*ND + c);
        cpa16(kl + r*144 + c*2, Kl_g + qkoff + (size_t)(kt + r)*ND + c);
        cpa16(vh + r*144 + c*2, Vth_g + voff + (size_t)r*NS + kt + c);
        cpa16(vl + r*144 + c*2, Vtl_g + voff + (size_t)r*NS + kt + c);
      }
      CP_COMMIT;
      CP_WAIT1;
    } else {
      CP_WAIT0;
    }
    __syncthreads();

    // ---- QK ----
    const unsigned kh_base = smem_u32(sm + F_KB(buf, 0));
    const unsigned kl_base = kh_base + 9216;

    float c[4][4];
#pragma unroll
    for (int nt = 0; nt < 4; nt++)
#pragma unroll
      for (int j = 0; j < 4; j++) c[nt][j] = 0.f;

#pragma unroll
    for (int ks = 0; ks < 64; ks += 16) {
      unsigned ah[4], al[4];
      ldsm_x4(ah[0], ah[1], ah[2], ah[3], qh_addr0 + ks*2);
      ldsm_x4(al[0], al[1], al[2], al[3], ql_addr0 + ks*2);
      unsigned bh00, bh01, bh10, bh11, bh20, bh21, bh30, bh31;
      unsigned bl00, bl01, bl10, bl11, bl20, bl21, bl30, bl31;
      ldsm_x4(bh00, bh01, bh10, bh11, kh_base + k_off0 + ks*2);
      ldsm_x4(bh20, bh21, bh30, bh31, kh_base + k_off1 + ks*2);
      ldsm_x4(bl00, bl01, bl10, bl11, kl_base + k_off0 + ks*2);
      ldsm_x4(bl20, bl21, bl30, bl31, kl_base + k_off1 + ks*2);
      mma16816(c[0], ah, bh00, bh01);
      mma16816(c[0], ah, bl00, bl01);
      mma16816(c[0], al, bh00, bh01);
      mma16816(c[1], ah, bh10, bh11);
      mma16816(c[1], ah, bl10, bl11);
      mma16816(c[1], al, bh10, bh11);
      mma16816(c[2], ah, bh20, bh21);
      mma16816(c[2], ah, bl20, bl21);
      mma16816(c[2], al, bh20, bh21);
      mma16816(c[3], ah, bh30, bh31);
      mma16816(c[3], ah, bl30, bl31);
      mma16816(c[3], al, bh30, bh31);
    }

    // ---- exp + sums + STG of unnormalized P ----
    float ee[4][4];
    float s0 = 0.f, s1 = 0.f;
    const int r0 = wq + g, r1 = wq + g + 8;
#pragma unroll
    for (int nt = 0; nt < 4; nt++) {
      int gcol = ch*64 + wk + nt*8 + tq*2;
      float e0 = __expf(c[nt][0] * 0.125f);
      float e1 = __expf(c[nt][1] * 0.125f);
      float e2 = __expf(c[nt][2] * 0.125f);
      float e3 = __expf(c[nt][3] * 0.125f);
      ee[nt][0] = e0; ee[nt][1] = e1; ee[nt][2] = e2; ee[nt][3] = e3;
      s0 += e0 + e1;
      s1 += e2 + e3;
      float2 p0; p0.x = e0; p0.y = e1;
      float2 p1; p1.x = e2; p1.y = e3;
      *(float2*)&Arows[(size_t)r0*NS + gcol] = p0;
      *(float2*)&Arows[(size_t)r1*NS + gcol] = p1;
    }
    s0 += __shfl_xor_sync(0xffffffffu, s0, 1);
    s0 += __shfl_xor_sync(0xffffffffu, s0, 2);
    s1 += __shfl_xor_sync(0xffffffffu, s1, 1);
    s1 += __shfl_xor_sync(0xffffffffu, s1, 2);
    if (tq == 0) {
      atomicAdd(&ssum[r0], s0);
      atomicAdd(&ssum[r1], s1);
    }

    // ---- PV: feed exp straight from registers ----
    const __nv_bfloat16* Vbh = (const __nv_bfloat16*)(sm + F_VB(buf, 0));
    const __nv_bfloat16* Vbl = (const __nv_bfloat16*)(sm + F_VB(buf, 1));
#pragma unroll
    for (int kt2 = 0; kt2 < 2; kt2++) {
      unsigned ap_h[4], ap_l[4];
      const int n0t = kt2*2;
      pack_hilo(ee[n0t  ][0], ee[n0t  ][1], ap_h[0], ap_l[0]);
      pack_hilo(ee[n0t  ][2], ee[n0t  ][3], ap_h[1], ap_l[1]);
      pack_hilo(ee[n0t+1][0], ee[n0t+1][1], ap_h[2], ap_l[2]);
      pack_hilo(ee[n0t+1][2], ee[n0t+1][3], ap_h[3], ap_l[3]);
      const int kkk = wk + kt2*16;
#pragma unroll
      for (int dt = 0; dt < 8; dt++) {
        const int vrow = dt*8 + g;
        unsigned b0h = *(const unsigned*)&Vbh[vrow*FLD + kkk + tq*2];
        unsigned b1h = *(const unsigned*)&Vbh[vrow*FLD + kkk + 8 + tq*2];
        unsigned b0l = *(const unsigned*)&Vbl[vrow*FLD + kkk + tq*2];
        unsigned b1l = *(const unsigned*)&Vbl[vrow*FLD + kkk + 8 + tq*2];
        mma16816(o[dt], ap_h, b0h, b1h);
        mma16816(o[dt], ap_l, b0h, b1h);
        mma16816(o[dt], ap_h, b0l, b1l);
      }
    }
    __syncthreads();
    buf ^= 1;
  }

  // ---- inv ----
  if (t < 64) sinv[t] = 1.0f / ssum[t];
  __syncthreads();

  // ---- cross-warp pair reduction (wk=32 warp dumps to scratch) ----
  float* scr = (float*)(sm + F_SCR);   // [wq/16][16 rows][68 stride]
  const int scrb = (wid >> 1) * 16 * 68;
  if (wid & 1) {
#pragma unroll
    for (int dt = 0; dt < 8; dt++) {
      scr[scrb + (g    )*68 + dt*8 + tq*2    ] = o[dt][0];
      scr[scrb + (g    )*68 + dt*8 + tq*2 + 1] = o[dt][1];
      scr[scrb + (g + 8)*68 + dt*8 + tq*2    ] = o[dt][2];
      scr[scrb + (g + 8)*68 + dt*8 + tq*2 + 1] = o[dt][3];
    }
  }
  __syncthreads();
  if ((wid & 1) == 0) {
    const float inv0 = sinv[wq + g];
    const float inv1 = sinv[wq + g + 8];
    const size_t xb0 = (size_t)(b*NS + q0 + wq + g    )*ND + h*NDK;
    const size_t xb1 = (size_t)(b*NS + q0 + wq + g + 8)*ND + h*NDK;
#pragma unroll
    for (int dt = 0; dt < 8; dt++) {
      int d0 = dt*8 + tq*2;
      float v00 = (o[dt][0] + scr[scrb + (g    )*68 + d0    ]) * inv0;
      float v01 = (o[dt][1] + scr[scrb + (g    )*68 + d0 + 1]) * inv0;
      float v10 = (o[dt][2] + scr[scrb + (g + 8)*68 + d0    ]) * inv1;
      float v11 = (o[dt][3] + scr[scrb + (g + 8)*68 + d0 + 1]) * inv1;
      unsigned h0, l0, h1, l1;
      pack_hilo(v00, v01, h0, l0);
      pack_hilo(v10, v11, h1, l1);
      *(unsigned*)&XhG[xb0 + d0] = h0;
      *(unsigned*)&XlG[xb0 + d0] = l0;
      *(unsigned*)&XhG[xb1 + d0] = h1;
      *(unsigned*)&XlG[xb1 + d0] = l1;
    }
  }

  // ---- normalize the CTA's own P strip (attn output) ----
  for (int i = t; i < 64*512; i += 256) {
    int row = i >> 9;
    int c4  = (i & 511) << 2;
    float inv = sinv[row];
    float* p = Arows + (size_t)row*NS + c4;
    float4 v = *(const float4*)p;
    v.x *= inv; v.y *= inv; v.z *= inv; v.w *= inv;
    *(float4*)p = v;
  }
}

// ---------------------------------------------------------------------------
extern "C" void kernel_launch(void* const* d_in, const int* in_sizes, int n_in,
                              void* d_out, int out_size)
{
  const float* q   = (const float*)d_in[0];
  const float* k   = (const float*)d_in[1];
  const float* v   = (const float*)d_in[2];
  const float* w_q = (const float*)d_in[3];
  const float* b_q = (const float*)d_in[4];
  const float* w_k = (const float*)d_in[5];
  const float* b_k = (const float*)d_in[6];
  const float* w_v = (const float*)d_in[7];
  const float* b_v = (const float*)d_in[8];
  const float* w_o = (const float*)d_in[9];
  const float* b_o = (const float*)d_in[10];

  __nv_bfloat16 *qh, *ql, *kh, *kl, *vth, *vtl, *ah, *al, *xh, *xl, *wh, *wl;
  cudaGetSymbolAddress((void**)&qh,  g_Qh);
  cudaGetSymbolAddress((void**)&ql,  g_Ql);
  cudaGetSymbolAddress((void**)&kh,  g_Kh);
  cudaGetSymbolAddress((void**)&kl,  g_Kl);
  cudaGetSymbolAddress((void**)&vth, g_Vth);
  cudaGetSymbolAddress((void**)&vtl, g_Vtl);
  cudaGetSymbolAddress((void**)&ah,  g_Ah);
  cudaGetSymbolAddress((void**)&al,  g_Al);
  cudaGetSymbolAddress((void**)&xh,  g_Xh);
  cudaGetSymbolAddress((void**)&xl,  g_Xl);
  cudaGetSymbolAddress((void**)&wh,  g_Wh);
  cudaGetSymbolAddress((void**)&wl,  g_Wl);

  const size_t OUT_E = (size_t)NB * NS * ND;
  float* outp  = (float*)d_out;
  float* attnp = outp + OUT_E;

  cudaFuncSetAttribute(linear_bf16_kernel, cudaFuncAttributeMaxDynamicSharedMemorySize, LB_SMEM);
  cudaFuncSetAttribute(attn_fused_kernel,  cudaFuncAttributeMaxDynamicSharedMemorySize, F_SMEM);

  const int NACT = NM*ND;
  const int GACT = (NACT/4 + 255)/256;
  const int GW   = (WSZ/4 + 255)/256;

  split_kernel<<<GW, 256>>>(w_q, wh + 0*WSZ, wl + 0*WSZ, WSZ);
  split_kernel<<<GW, 256>>>(w_k, wh + 1*WSZ, wl + 1*WSZ, WSZ);
  split_kernel<<<GW, 256>>>(w_v, wh + 2*WSZ, wl + 2*WSZ, WSZ);
  split_kernel<<<GW, 256>>>(w_o, wh + 3*WSZ, wl + 3*WSZ, WSZ);

  dim3 gproj(ND/64, NM/128);   // (12, 32)
  split_kernel<<<GACT, 256>>>(q, ah, al, NACT);
  linear_bf16_kernel<<<gproj, 256, LB_SMEM>>>(ah, al, wh + 0*WSZ, wl + 0*WSZ,
                                              b_q, nullptr, qh, ql, NM, ND, ND, 1);
  split_kernel<<<GACT, 256>>>(k, ah, al, NACT);
  linear_bf16_kernel<<<gproj, 256, LB_SMEM>>>(ah, al, wh + 1*WSZ, wl + 1*WSZ,
                                              b_k, nullptr, kh, kl, NM, ND, ND, 1);
  split_kernel<<<GACT, 256>>>(v, ah, al, NACT);
  linear_bf16_kernel<<<gproj, 256, LB_SMEM>>>(ah, al, wh + 2*WSZ, wl + 2*WSZ,
                                              b_v, nullptr, vth, vtl, NM, ND, ND, 2);

  dim3 gattn(NS/64, NB*NH);    // (32, 24)
  attn_fused_kernel<<<gattn, 256, F_SMEM>>>(qh, ql, kh, kl, vth, vtl, attnp, xh, xl);

  linear_bf16_kernel<<<gproj, 256, LB_SMEM>>>(xh, xl, wh + 3*WSZ, wl + 3*WSZ,
                                              b_o, outp, nullptr, nullptr, NM, ND, ND, 0);
}

// round 16
// speedup vs baseline: 1.0614x; 1.0418x over previous
#include <cuda_runtime.h>
#include <cuda_bf16.h>
#include <mma.h>
#include <cstdint>

using namespace nvcuda;

#define NB 2
#define NS 2048
#define ND 768
#define NH 12
#define NDK 64
#define NM (NB*NS)
#define WSZ (ND*ND)

// ---- device-global scratch (allocation-free rule) ----
__device__ __nv_bfloat16 g_Qh[NM*ND], g_Ql[NM*ND];
__device__ __nv_bfloat16 g_Kh[NM*ND], g_Kl[NM*ND];
__device__ __nv_bfloat16 g_Vth[NM*ND], g_Vtl[NM*ND];   // [bh][d][s]
__device__ __nv_bfloat16 g_Ah[NM*ND], g_Al[NM*ND];     // split activations in
__device__ __nv_bfloat16 g_Xh[NM*ND], g_Xl[NM*ND];     // split attn out
__device__ __nv_bfloat16 g_Wh[4*WSZ], g_Wl[4*WSZ];     // split weights
__device__ float g_inv[NB*NH*NS];

// ---------------------------------------------------------------------------
__device__ __forceinline__ void split1(float x, __nv_bfloat16& h, __nv_bfloat16& l) {
  h = __float2bfloat16_rn(x);
  l = __float2bfloat16_rn(x - __bfloat162float(h));
}
__device__ __forceinline__ void split4(float4 v, __nv_bfloat16* hrow,
                                       __nv_bfloat16* lrow, int k) {
  __nv_bfloat16 h0,l0,h1,l1,h2,l2,h3,l3;
  split1(v.x,h0,l0); split1(v.y,h1,l1); split1(v.z,h2,l2); split1(v.w,h3,l3);
  *(__nv_bfloat162*)(hrow+k)   = __halves2bfloat162(h0,h1);
  *(__nv_bfloat162*)(hrow+k+2) = __halves2bfloat162(h2,h3);
  *(__nv_bfloat162*)(lrow+k)   = __halves2bfloat162(l0,l1);
  *(__nv_bfloat162*)(lrow+k+2) = __halves2bfloat162(l2,l3);
}
// pack two floats -> bf16x2 (hi) and residual bf16x2 (lo)
__device__ __forceinline__ void pack_hilo(float a, float b, unsigned& hi, unsigned& lo) {
  __nv_bfloat16 ha = __float2bfloat16_rn(a);
  __nv_bfloat16 hb = __float2bfloat16_rn(b);
  __nv_bfloat16 la = __float2bfloat16_rn(a - __bfloat162float(ha));
  __nv_bfloat16 lb = __float2bfloat16_rn(b - __bfloat162float(hb));
  __nv_bfloat162 th = __halves2bfloat162(ha, hb);
  __nv_bfloat162 tl = __halves2bfloat162(la, lb);
  hi = *(unsigned*)&th;
  lo = *(unsigned*)&tl;
}

typedef wmma::fragment<wmma::matrix_a, 16,16,16, __nv_bfloat16, wmma::row_major> FragA;
typedef wmma::fragment<wmma::matrix_b, 16,16,16, __nv_bfloat16, wmma::col_major> FragB;
typedef wmma::fragment<wmma::accumulator, 16,16,16, float> FragC;

__device__ __forceinline__ void mma3(FragC& c, const FragA& ah, const FragA& al,
                                     const FragB& bh, const FragB& bl) {
  wmma::mma_sync(c, ah, bh, c);
  wmma::mma_sync(c, ah, bl, c);
  wmma::mma_sync(c, al, bh, c);
}

// raw m16n8k16 bf16 mma, fp32 accum
__device__ __forceinline__ void mma16816(float* c, const unsigned* a, unsigned b0, unsigned b1) {
  asm volatile(
    "mma.sync.aligned.m16n8k16.row.col.f32.bf16.bf16.f32 "
    "{%0,%1,%2,%3}, {%4,%5,%6,%7}, {%8,%9}, {%0,%1,%2,%3};\n"
    : "+f"(c[0]), "+f"(c[1]), "+f"(c[2]), "+f"(c[3])
    : "r"(a[0]), "r"(a[1]), "r"(a[2]), "r"(a[3]), "r"(b0), "r"(b1));
}

__device__ __forceinline__ void ldsm_x4(unsigned& r0, unsigned& r1,
                                        unsigned& r2, unsigned& r3, unsigned addr) {
  asm volatile("ldmatrix.sync.aligned.m8n8.x4.shared.b16 {%0,%1,%2,%3}, [%4];\n"
    : "=r"(r0), "=r"(r1), "=r"(r2), "=r"(r3) : "r"(addr));
}

__device__ __forceinline__ unsigned int smem_u32(const void* p) {
  return (unsigned int)__cvta_generic_to_shared(p);
}
__device__ __forceinline__ void cpa16(unsigned int dst, const void* src) {
  asm volatile("cp.async.cg.shared.global [%0], [%1], 16;\n" :: "r"(dst), "l"(src));
}
#define CP_COMMIT asm volatile("cp.async.commit_group;\n")
#define CP_WAIT0  asm volatile("cp.async.wait_group 0;\n")
#define CP_WAIT1  asm volatile("cp.async.wait_group 1;\n")

// ---------------------------------------------------------------------------
// split_kernel: fp32 -> bf16 hi/lo, elementwise (n % 4 == 0)
// ---------------------------------------------------------------------------
__global__ __launch_bounds__(256) void split_kernel(
    const float* __restrict__ in, __nv_bfloat16* __restrict__ h,
    __nv_bfloat16* __restrict__ l, int n)
{
  int i = (blockIdx.x*blockDim.x + threadIdx.x) << 2;
  if (i < n) {
    float4 v = *(const float4*)(in + i);
    split4(v, h, l, i);
  }
}

// ---------------------------------------------------------------------------
// linear_bf16: pre-split operands, cp.async double-buffer, 1 barrier/chunk.
// Optional tail: grid-stride normalization of the attn buffer (runs only in
// the final output projection; DRAM-streaming overlaps other CTAs' GEMMs).
// ---------------------------------------------------------------------------
#define LB_LD 40
#define LB_XB(buf,hl) ((buf)*30720 + (hl)*10240)
#define LB_WB(buf,hl) ((buf)*30720 + 20480 + (hl)*5120)
#define LB_CLD 68
#define LB_SMEM 61440

__global__ __launch_bounds__(256, 3) void linear_bf16_kernel(
    const __nv_bfloat16* __restrict__ Xh_g, const __nv_bfloat16* __restrict__ Xl_g,
    const __nv_bfloat16* __restrict__ Wh_g, const __nv_bfloat16* __restrict__ Wl_g,
    const float* __restrict__ bias, float* __restrict__ Out,
    __nv_bfloat16* __restrict__ OutH, __nv_bfloat16* __restrict__ OutL,
    int M, int N, int K, int mode,
    float* __restrict__ attn_n, const float* __restrict__ inv_all)
{
  extern __shared__ char sm[];
  float* Cs = (float*)sm;

  const int m0 = blockIdx.y * 128;
  const int n0 = blockIdx.x * 64;
  const int t  = threadIdx.x;
  const int wid = t >> 5;
  const int wm  = wid >> 1;
  const int wn  = wid & 1;

  {
#pragma unroll
    for (int hl = 0; hl < 2; hl++) {
      const __nv_bfloat16* Xs = hl ? Xl_g : Xh_g;
      unsigned int xb = smem_u32(sm + LB_XB(0,hl));
#pragma unroll
      for (int i = 0; i < 2; i++) {
        int seg = t + 256*i;
        int r = seg >> 2, cs = seg & 3;
        cpa16(xb + r*80 + cs*16, Xs + (size_t)(m0 + r)*K + cs*8);
      }
      const __nv_bfloat16* Ws = hl ? Wl_g : Wh_g;
      unsigned int wb = smem_u32(sm + LB_WB(0,hl));
      {
        int r = t >> 2, cs = t & 3;
        cpa16(wb + r*80 + cs*16, Ws + (size_t)(n0 + r)*K + cs*8);
      }
    }
    CP_COMMIT;
  }

  FragC c[2][2];
#pragma unroll
  for (int i = 0; i < 2; i++)
#pragma unroll
    for (int j = 0; j < 2; j++) wmma::fill_fragment(c[i][j], 0.0f);

  const int NCH = K / 32;
  int buf = 0;
  for (int ch = 0; ch < NCH; ch++) {
    CP_WAIT0;
    __syncthreads();
    if (ch + 1 < NCH) {
      int k0 = (ch + 1) * 32;
      int nb = buf ^ 1;
#pragma unroll
      for (int hl = 0; hl < 2; hl++) {
        const __nv_bfloat16* Xs = hl ? Xl_g : Xh_g;
        unsigned int xb = smem_u32(sm + LB_XB(nb,hl));
#pragma unroll
        for (int i = 0; i < 2; i++) {
          int seg = t + 256*i;
          int r = seg >> 2, cs = seg & 3;
          cpa16(xb + r*80 + cs*16, Xs + (size_t)(m0 + r)*K + k0 + cs*8);
        }
        const __nv_bfloat16* Ws = hl ? Wl_g : Wh_g;
        unsigned int wb = smem_u32(sm + LB_WB(nb,hl));
        {
          int r = t >> 2, cs = t & 3;
          cpa16(wb + r*80 + cs*16, Ws + (size_t)(n0 + r)*K + k0 + cs*8);
        }
      }
      CP_COMMIT;
    }
    const __nv_bfloat16* Xh = (const __nv_bfloat16*)(sm + LB_XB(buf,0));
    const __nv_bfloat16* Xl = (const __nv_bfloat16*)(sm + LB_XB(buf,1));
    const __nv_bfloat16* Wh = (const __nv_bfloat16*)(sm + LB_WB(buf,0));
    const __nv_bfloat16* Wl = (const __nv_bfloat16*)(sm + LB_WB(buf,1));
#pragma unroll
    for (int ks = 0; ks < 32; ks += 16) {
      FragA ah[2], al[2];
      FragB bh[2], bl[2];
#pragma unroll
      for (int i = 0; i < 2; i++) {
        wmma::load_matrix_sync(ah[i], Xh + (wm*32 + i*16)*LB_LD + ks, LB_LD);
        wmma::load_matrix_sync(al[i], Xl + (wm*32 + i*16)*LB_LD + ks, LB_LD);
      }
#pragma unroll
      for (int j = 0; j < 2; j++) {
        wmma::load_matrix_sync(bh[j], Wh + (wn*32 + j*16)*LB_LD + ks, LB_LD);
        wmma::load_matrix_sync(bl[j], Wl + (wn*32 + j*16)*LB_LD + ks, LB_LD);
      }
#pragma unroll
      for (int i = 0; i < 2; i++)
#pragma unroll
        for (int j = 0; j < 2; j++) mma3(c[i][j], ah[i], al[i], bh[j], bl[j]);
    }
    buf ^= 1;
  }
  __syncthreads();
#pragma unroll
  for (int i = 0; i < 2; i++)
#pragma unroll
    for (int j = 0; j < 2; j++)
      wmma::store_matrix_sync(Cs + (wm*32 + i*16)*LB_CLD + wn*32 + j*16,
                              c[i][j], LB_CLD, wmma::mem_row_major);
  __syncthreads();

  if (mode == 0) {
    for (int i = t; i < 128*16; i += 256) {
      int row = i >> 4;
      int c4  = (i & 15) << 2;
      float4 v = *(const float4*)&Cs[row*LB_CLD + c4];
      float4 bb = *(const float4*)(bias + n0 + c4);
      v.x += bb.x; v.y += bb.y; v.z += bb.z; v.w += bb.w;
      *(float4*)&Out[(size_t)(m0 + row)*N + n0 + c4] = v;
    }
  } else if (mode == 1) {
    for (int i = t; i < 128*16; i += 256) {
      int row = i >> 4;
      int c4  = (i & 15) << 2;
      float4 v = *(const float4*)&Cs[row*LB_CLD + c4];
      float4 bb = *(const float4*)(bias + n0 + c4);
      v.x += bb.x; v.y += bb.y; v.z += bb.z; v.w += bb.w;
      size_t base = (size_t)(m0 + row)*N + n0 + c4;
      split4(v, OutH + base, OutL + base, 0);
    }
  } else {
    for (int j = t; j < 64*128; j += 256) {
      int d   = j >> 7;
      int row = j & 127;
      float val = Cs[row*LB_CLD + d] + bias[n0 + d];
      __nv_bfloat16 h, l;
      split1(val, h, l);
      int m  = m0 + row;
      int bb = m >> 11;
      int s  = m & 2047;
      int n  = n0 + d;
      int hh = n >> 6;
      int dd = n & 63;
      size_t idx = ((size_t)(bb*NH + hh)*NDK + dd)*NS + s;
      OutH[idx] = h;
      OutL[idx] = l;
    }
  }

  // ---- fused attn-normalization tail (final projection only) ----
  if (attn_n) {
    // 384 CTAs cover NB*NH*NS = 49152 rows -> 128 rows each
    int cta = blockIdx.y * gridDim.x + blockIdx.x;
    int row0 = cta * 128;
#pragma unroll 1
    for (int rr = 0; rr < 128; rr++) {
      int row = row0 + rr;
      float inv = inv_all[row];
      float* p = attn_n + (size_t)row * NS;
      // 2048 floats = 512 float4; 256 threads -> 2 each
#pragma unroll
      for (int i = 0; i < 2; i++) {
        int idx = (t + 256*i) << 2;
        float4 v = *(const float4*)(p + idx);
        v.x *= inv; v.y *= inv; v.z *= inv; v.w *= inv;
        *(float4*)(p + idx) = v;
      }
    }
  }
}

// ---------------------------------------------------------------------------
// Fused attention: CTA = 64 q x one (b,h), chunks of 64 keys.
// QK mma (LDSM) -> exp in regs -> STG unnorm P + row sums -> PV mma from
// registers vs double-buffered V. Tail: pair-reduce + scale -> split X write;
// inv written to global (normalization happens in the final linear's tail).
// ---------------------------------------------------------------------------
#define FLD 72
#define F_QHO 0
#define F_QLO 9216
#define F_KB(buf,hl) (18432 + (buf)*18432 + (hl)*9216)
#define F_VB(buf,hl) (55296 + (buf)*18432 + (hl)*9216)
#define F_SUMO 92160
#define F_INVO 92416
#define F_SCR  18432              // reduction scratch aliases K ring
#define F_SMEM 92672

__global__ __launch_bounds__(256, 2) void attn_fused_kernel(
    const __nv_bfloat16* __restrict__ Qh_g, const __nv_bfloat16* __restrict__ Ql_g,
    const __nv_bfloat16* __restrict__ Kh_g, const __nv_bfloat16* __restrict__ Kl_g,
    const __nv_bfloat16* __restrict__ Vth_g, const __nv_bfloat16* __restrict__ Vtl_g,
    float* __restrict__ attn_out, float* __restrict__ inv_out,
    __nv_bfloat16* __restrict__ XhG, __nv_bfloat16* __restrict__ XlG)
{
  extern __shared__ char sm[];
  float* ssum = (float*)(sm + F_SUMO);
  float* sinv = (float*)(sm + F_INVO);

  const int t  = threadIdx.x;
  const int q0 = blockIdx.x * 64;
  const int bh = blockIdx.y;
  const int b  = bh / NH, h = bh % NH;
  const int wid = t >> 5;
  const int lane = t & 31;
  const int g  = lane >> 2;
  const int tq = lane & 3;
  const int wq = (wid >> 1) * 16;
  const int wk = (wid & 1) * 32;

  const int sub = lane >> 3, l7 = lane & 7;
  const unsigned qh_addr0 = smem_u32(sm + F_QHO) +
      (unsigned)(((wq + (sub & 1)*8 + l7)*FLD + (sub >> 1)*8) * 2);
  const unsigned ql_addr0 = qh_addr0 + (F_QLO - F_QHO);
  const unsigned k_off0 = (unsigned)(((wk + (sub >> 1)*8 + l7)*FLD + (sub & 1)*8) * 2);
  const unsigned k_off1 = k_off0 + 16*FLD*2;

  const size_t qkoff = ((size_t)b*NS)*ND + h*NDK;
  const size_t voff  = (size_t)bh*NDK*NS;
  float* Arows = attn_out + ((size_t)bh*NS + q0)*NS;

  if (t < 64) ssum[t] = 0.f;

  {
    unsigned int qh = smem_u32(sm + F_QHO), ql = smem_u32(sm + F_QLO);
#pragma unroll
    for (int i = 0; i < 2; i++) {
      int f = t + 256*i;
      int r = f >> 3;
      int c = (f & 7) * 8;
      cpa16(qh + r*144 + c*2, Qh_g + qkoff + (size_t)(q0 + r)*ND + c);
      cpa16(ql + r*144 + c*2, Ql_g + qkoff + (size_t)(q0 + r)*ND + c);
    }
    unsigned int kh = smem_u32(sm + F_KB(0,0)), kl = smem_u32(sm + F_KB(0,1));
    unsigned int vh = smem_u32(sm + F_VB(0,0)), vl = smem_u32(sm + F_VB(0,1));
#pragma unroll
    for (int i = 0; i < 2; i++) {
      int f = t + 256*i;
      int r = f >> 3;
      int c = (f & 7) * 8;
      cpa16(kh + r*144 + c*2, Kh_g + qkoff + (size_t)r*ND + c);
      cpa16(kl + r*144 + c*2, Kl_g + qkoff + (size_t)r*ND + c);
      cpa16(vh + r*144 + c*2, Vth_g + voff + (size_t)r*NS + c);
      cpa16(vl + r*144 + c*2, Vtl_g + voff + (size_t)r*NS + c);
    }
    CP_COMMIT;
  }

  float o[8][4];
#pragma unroll
  for (int dt = 0; dt < 8; dt++)
#pragma unroll
    for (int j = 0; j < 4; j++) o[dt][j] = 0.f;

  int buf = 0;
  for (int ch = 0; ch < 32; ch++) {
    if (ch < 31) {
      int kt = (ch + 1) * 64;
      int nb = buf ^ 1;
      unsigned int kh = smem_u32(sm + F_KB(nb,0)), kl = smem_u32(sm + F_KB(nb,1));
      unsigned int vh = smem_u32(sm + F_VB(nb,0)), vl = smem_u32(sm + F_VB(nb,1));
#pragma unroll
      for (int i = 0; i < 2; i++) {
        int f = t + 256*i;
        int r = f >> 3;
        int c = (f & 7) * 8;
        cpa16(kh + r*144 + c*2, Kh_g + qkoff + (size_t)(kt + r)*ND + c);
        cpa16(kl + r*144 + c*2, Kl_g + qkoff + (size_t)(kt + r)*ND + c);
        cpa16(vh + r*144 + c*2, Vth_g + voff + (size_t)r*NS + kt + c);
        cpa16(vl + r*144 + c*2, Vtl_g + voff + (size_t)r*NS + kt + c);
      }
      CP_COMMIT;
      CP_WAIT1;
    } else {
      CP_WAIT0;
    }
    __syncthreads();

    // ---- QK ----
    const unsigned kh_base = smem_u32(sm + F_KB(buf, 0));
    const unsigned kl_base = kh_base + 9216;

    float c[4][4];
#pragma unroll
    for (int nt = 0; nt < 4; nt++)
#pragma unroll
      for (int j = 0; j < 4; j++) c[nt][j] = 0.f;

#pragma unroll
    for (int ks = 0; ks < 64; ks += 16) {
      unsigned ah[4], al[4];
      ldsm_x4(ah[0], ah[1], ah[2], ah[3], qh_addr0 + ks*2);
      ldsm_x4(al[0], al[1], al[2], al[3], ql_addr0 + ks*2);
      unsigned bh00, bh01, bh10, bh11, bh20, bh21, bh30, bh31;
      unsigned bl00, bl01, bl10, bl11, bl20, bl21, bl30, bl31;
      ldsm_x4(bh00, bh01, bh10, bh11, kh_base + k_off0 + ks*2);
      ldsm_x4(bh20, bh21, bh30, bh31, kh_base + k_off1 + ks*2);
      ldsm_x4(bl00, bl01, bl10, bl11, kl_base + k_off0 + ks*2);
      ldsm_x4(bl20, bl21, bl30, bl31, kl_base + k_off1 + ks*2);
      mma16816(c[0], ah, bh00, bh01);
      mma16816(c[0], ah, bl00, bl01);
      mma16816(c[0], al, bh00, bh01);
      mma16816(c[1], ah, bh10, bh11);
      mma16816(c[1], ah, bl10, bl11);
      mma16816(c[1], al, bh10, bh11);
      mma16816(c[2], ah, bh20, bh21);
      mma16816(c[2], ah, bl20, bl21);
      mma16816(c[2], al, bh20, bh21);
      mma16816(c[3], ah, bh30, bh31);
      mma16816(c[3], ah, bl30, bl31);
      mma16816(c[3], al, bh30, bh31);
    }

    // ---- exp + sums + STG of unnormalized P ----
    float ee[4][4];
    float s0 = 0.f, s1 = 0.f;
    const int r0 = wq + g, r1 = wq + g + 8;
#pragma unroll
    for (int nt = 0; nt < 4; nt++) {
      int gcol = ch*64 + wk + nt*8 + tq*2;
      float e0 = __expf(c[nt][0] * 0.125f);
      float e1 = __expf(c[nt][1] * 0.125f);
      float e2 = __expf(c[nt][2] * 0.125f);
      float e3 = __expf(c[nt][3] * 0.125f);
      ee[nt][0] = e0; ee[nt][1] = e1; ee[nt][2] = e2; ee[nt][3] = e3;
      s0 += e0 + e1;
      s1 += e2 + e3;
      float2 p0; p0.x = e0; p0.y = e1;
      float2 p1; p1.x = e2; p1.y = e3;
      *(float2*)&Arows[(size_t)r0*NS + gcol] = p0;
      *(float2*)&Arows[(size_t)r1*NS + gcol] = p1;
    }
    s0 += __shfl_xor_sync(0xffffffffu, s0, 1);
    s0 += __shfl_xor_sync(0xffffffffu, s0, 2);
    s1 += __shfl_xor_sync(0xffffffffu, s1, 1);
    s1 += __shfl_xor_sync(0xffffffffu, s1, 2);
    if (tq == 0) {
      atomicAdd(&ssum[r0], s0);
      atomicAdd(&ssum[r1], s1);
    }

    // ---- PV: feed exp straight from registers ----
    const __nv_bfloat16* Vbh = (const __nv_bfloat16*)(sm + F_VB(buf, 0));
    const __nv_bfloat16* Vbl = (const __nv_bfloat16*)(sm + F_VB(buf, 1));
#pragma unroll
    for (int kt2 = 0; kt2 < 2; kt2++) {
      unsigned ap_h[4], ap_l[4];
      const int n0t = kt2*2;
      pack_hilo(ee[n0t  ][0], ee[n0t  ][1], ap_h[0], ap_l[0]);
      pack_hilo(ee[n0t  ][2], ee[n0t  ][3], ap_h[1], ap_l[1]);
      pack_hilo(ee[n0t+1][0], ee[n0t+1][1], ap_h[2], ap_l[2]);
      pack_hilo(ee[n0t+1][2], ee[n0t+1][3], ap_h[3], ap_l[3]);
      const int kkk = wk + kt2*16;
#pragma unroll
      for (int dt = 0; dt < 8; dt++) {
        const int vrow = dt*8 + g;
        unsigned b0h = *(const unsigned*)&Vbh[vrow*FLD + kkk + tq*2];
        unsigned b1h = *(const unsigned*)&Vbh[vrow*FLD + kkk + 8 + tq*2];
        unsigned b0l = *(const unsigned*)&Vbl[vrow*FLD + kkk + tq*2];
        unsigned b1l = *(const unsigned*)&Vbl[vrow*FLD + kkk + 8 + tq*2];
        mma16816(o[dt], ap_h, b0h, b1h);
        mma16816(o[dt], ap_l, b0h, b1h);
        mma16816(o[dt], ap_h, b0l, b1l);
      }
    }
    __syncthreads();
    buf ^= 1;
  }

  // ---- inv ----
  if (t < 64) {
    float iv = 1.0f / ssum[t];
    sinv[t] = iv;
    inv_out[(size_t)bh*NS + q0 + t] = iv;
  }
  __syncthreads();

  // ---- cross-warp pair reduction (wk=32 warp dumps to scratch) ----
  float* scr = (float*)(sm + F_SCR);   // [wq/16][16 rows][68 stride]
  const int scrb = (wid >> 1) * 16 * 68;
  if (wid & 1) {
#pragma unroll
    for (int dt = 0; dt < 8; dt++) {
      scr[scrb + (g    )*68 + dt*8 + tq*2    ] = o[dt][0];
      scr[scrb + (g    )*68 + dt*8 + tq*2 + 1] = o[dt][1];
      scr[scrb + (g + 8)*68 + dt*8 + tq*2    ] = o[dt][2];
      scr[scrb + (g + 8)*68 + dt*8 + tq*2 + 1] = o[dt][3];
    }
  }
  __syncthreads();
  if ((wid & 1) == 0) {
    const float inv0 = sinv[wq + g];
    const float inv1 = sinv[wq + g + 8];
    const size_t xb0 = (size_t)(b*NS + q0 + wq + g    )*ND + h*NDK;
    const size_t xb1 = (size_t)(b*NS + q0 + wq + g + 8)*ND + h*NDK;
#pragma unroll
    for (int dt = 0; dt < 8; dt++) {
      int d0 = dt*8 + tq*2;
      float v00 = (o[dt][0] + scr[scrb + (g    )*68 + d0    ]) * inv0;
      float v01 = (o[dt][1] + scr[scrb + (g    )*68 + d0 + 1]) * inv0;
      float v10 = (o[dt][2] + scr[scrb + (g + 8)*68 + d0    ]) * inv1;
      float v11 = (o[dt][3] + scr[scrb + (g + 8)*68 + d0 + 1]) * inv1;
      unsigned h0, l0, h1, l1;
      pack_hilo(v00, v01, h0, l0);
      pack_hilo(v10, v11, h1, l1);
      *(unsigned*)&XhG[xb0 + d0] = h0;
      *(unsigned*)&XlG[xb0 + d0] = l0;
      *(unsigned*)&XhG[xb1 + d0] = h1;
      *(unsigned*)&XlG[xb1 + d0] = l1;
    }
  }
}

// ---------------------------------------------------------------------------
extern "C" void kernel_launch(void* const* d_in, const int* in_sizes, int n_in,
                              void* d_out, int out_size)
{
  const float* q   = (const float*)d_in[0];
  const float* k   = (const float*)d_in[1];
  const float* v   = (const float*)d_in[2];
  const float* w_q = (const float*)d_in[3];
  const float* b_q = (const float*)d_in[4];
  const float* w_k = (const float*)d_in[5];
  const float* b_k = (const float*)d_in[6];
  const float* w_v = (const float*)d_in[7];
  const float* b_v = (const float*)d_in[8];
  const float* w_o = (const float*)d_in[9];
  const float* b_o = (const float*)d_in[10];

  __nv_bfloat16 *qh, *ql, *kh, *kl, *vth, *vtl, *ah, *al, *xh, *xl, *wh, *wl;
  float *ginv;
  cudaGetSymbolAddress((void**)&qh,  g_Qh);
  cudaGetSymbolAddress((void**)&ql,  g_Ql);
  cudaGetSymbolAddress((void**)&kh,  g_Kh);
  cudaGetSymbolAddress((void**)&kl,  g_Kl);
  cudaGetSymbolAddress((void**)&vth, g_Vth);
  cudaGetSymbolAddress((void**)&vtl, g_Vtl);
  cudaGetSymbolAddress((void**)&ah,  g_Ah);
  cudaGetSymbolAddress((void**)&al,  g_Al);
  cudaGetSymbolAddress((void**)&xh,  g_Xh);
  cudaGetSymbolAddress((void**)&xl,  g_Xl);
  cudaGetSymbolAddress((void**)&wh,  g_Wh);
  cudaGetSymbolAddress((void**)&wl,  g_Wl);
  cudaGetSymbolAddress((void**)&ginv, g_inv);

  const size_t OUT_E = (size_t)NB * NS * ND;
  float* outp  = (float*)d_out;
  float* attnp = outp + OUT_E;

  cudaFuncSetAttribute(linear_bf16_kernel, cudaFuncAttributeMaxDynamicSharedMemorySize, LB_SMEM);
  cudaFuncSetAttribute(attn_fused_kernel,  cudaFuncAttributeMaxDynamicSharedMemorySize, F_SMEM);

  const int NACT = NM*ND;
  const int GACT = (NACT/4 + 255)/256;
  const int GW   = (WSZ/4 + 255)/256;

  split_kernel<<<GW, 256>>>(w_q, wh + 0*WSZ, wl + 0*WSZ, WSZ);
  split_kernel<<<GW, 256>>>(w_k, wh + 1*WSZ, wl + 1*WSZ, WSZ);
  split_kernel<<<GW, 256>>>(w_v, wh + 2*WSZ, wl + 2*WSZ, WSZ);
  split_kernel<<<GW, 256>>>(w_o, wh + 3*WSZ, wl + 3*WSZ, WSZ);

  dim3 gproj(ND/64, NM/128);   // (12, 32)
  split_kernel<<<GACT, 256>>>(q, ah, al, NACT);
  linear_bf16_kernel<<<gproj, 256, LB_SMEM>>>(ah, al, wh + 0*WSZ, wl + 0*WSZ,
      b_q, nullptr, qh, ql, NM, ND, ND, 1, nullptr, nullptr);
  split_kernel<<<GACT, 256>>>(k, ah, al, NACT);
  linear_bf16_kernel<<<gproj, 256, LB_SMEM>>>(ah, al, wh + 1*WSZ, wl + 1*WSZ,
      b_k, nullptr, kh, kl, NM, ND, ND, 1, nullptr, nullptr);
  split_kernel<<<GACT, 256>>>(v, ah, al, NACT);
  linear_bf16_kernel<<<gproj, 256, LB_SMEM>>>(ah, al, wh + 2*WSZ, wl + 2*WSZ,
      b_v, nullptr, vth, vtl, NM, ND, ND, 2, nullptr, nullptr);

  dim3 gattn(NS/64, NB*NH);    // (32, 24)
  attn_fused_kernel<<<gattn, 256, F_SMEM>>>(qh, ql, kh, kl, vth, vtl, attnp, ginv, xh, xl);

  // final projection + fused attn normalization tail
  linear_bf16_kernel<<<gproj, 256, LB_SMEM>>>(xh, xl, wh + 3*WSZ, wl + 3*WSZ,
      b_o, outp, nullptr, nullptr, NM, ND, ND, 0, attnp, ginv);
}

// round 17
// speedup vs baseline: 1.1386x; 1.0727x over previous
#include <cuda_runtime.h>
#include <cuda_bf16.h>
#include <mma.h>
#include <cstdint>

using namespace nvcuda;

#define NB 2
#define NS 2048
#define ND 768
#define NH 12
#define NDK 64
#define NM (NB*NS)
#define WSZ (ND*ND)
#define NACT (NM*ND)

// ---- device-global scratch (allocation-free rule) ----
__device__ __nv_bfloat16 g_Qh[NM*ND], g_Ql[NM*ND];
__device__ __nv_bfloat16 g_Kh[NM*ND], g_Kl[NM*ND];
__device__ __nv_bfloat16 g_Vth[NM*ND], g_Vtl[NM*ND];   // [bh][d][s]
__device__ __nv_bfloat16 g_Ah[NM*ND], g_Al[NM*ND];     // split q activations
__device__ __nv_bfloat16 g_Bh[NM*ND], g_Bl[NM*ND];     // split k activations
__device__ __nv_bfloat16 g_Ch[NM*ND], g_Cl[NM*ND];     // split v activations
__device__ __nv_bfloat16 g_Xh[NM*ND], g_Xl[NM*ND];     // split attn out
__device__ __nv_bfloat16 g_Wh[4*WSZ], g_Wl[4*WSZ];     // split weights
__device__ float g_inv[NB*NH*NS];

// ---------------------------------------------------------------------------
__device__ __forceinline__ void split1(float x, __nv_bfloat16& h, __nv_bfloat16& l) {
  h = __float2bfloat16_rn(x);
  l = __float2bfloat16_rn(x - __bfloat162float(h));
}
__device__ __forceinline__ void split4(float4 v, __nv_bfloat16* hrow,
                                       __nv_bfloat16* lrow, int k) {
  __nv_bfloat16 h0,l0,h1,l1,h2,l2,h3,l3;
  split1(v.x,h0,l0); split1(v.y,h1,l1); split1(v.z,h2,l2); split1(v.w,h3,l3);
  *(__nv_bfloat162*)(hrow+k)   = __halves2bfloat162(h0,h1);
  *(__nv_bfloat162*)(hrow+k+2) = __halves2bfloat162(h2,h3);
  *(__nv_bfloat162*)(lrow+k)   = __halves2bfloat162(l0,l1);
  *(__nv_bfloat162*)(lrow+k+2) = __halves2bfloat162(l2,l3);
}
// pack two floats -> bf16x2 (hi) and residual bf16x2 (lo)
__device__ __forceinline__ void pack_hilo(float a, float b, unsigned& hi, unsigned& lo) {
  __nv_bfloat16 ha = __float2bfloat16_rn(a);
  __nv_bfloat16 hb = __float2bfloat16_rn(b);
  __nv_bfloat16 la = __float2bfloat16_rn(a - __bfloat162float(ha));
  __nv_bfloat16 lb = __float2bfloat16_rn(b - __bfloat162float(hb));
  __nv_bfloat162 th = __halves2bfloat162(ha, hb);
  __nv_bfloat162 tl = __halves2bfloat162(la, lb);
  hi = *(unsigned*)&th;
  lo = *(unsigned*)&tl;
}

typedef wmma::fragment<wmma::matrix_a, 16,16,16, __nv_bfloat16, wmma::row_major> FragA;
typedef wmma::fragment<wmma::matrix_b, 16,16,16, __nv_bfloat16, wmma::col_major> FragB;
typedef wmma::fragment<wmma::accumulator, 16,16,16, float> FragC;

__device__ __forceinline__ void mma3(FragC& c, const FragA& ah, const FragA& al,
                                     const FragB& bh, const FragB& bl) {
  wmma::mma_sync(c, ah, bh, c);
  wmma::mma_sync(c, ah, bl, c);
  wmma::mma_sync(c, al, bh, c);
}

// raw m16n8k16 bf16 mma, fp32 accum
__device__ __forceinline__ void mma16816(float* c, const unsigned* a, unsigned b0, unsigned b1) {
  asm volatile(
    "mma.sync.aligned.m16n8k16.row.col.f32.bf16.bf16.f32 "
    "{%0,%1,%2,%3}, {%4,%5,%6,%7}, {%8,%9}, {%0,%1,%2,%3};\n"
    : "+f"(c[0]), "+f"(c[1]), "+f"(c[2]), "+f"(c[3])
    : "r"(a[0]), "r"(a[1]), "r"(a[2]), "r"(a[3]), "r"(b0), "r"(b1));
}

__device__ __forceinline__ void ldsm_x4(unsigned& r0, unsigned& r1,
                                        unsigned& r2, unsigned& r3, unsigned addr) {
  asm volatile("ldmatrix.sync.aligned.m8n8.x4.shared.b16 {%0,%1,%2,%3}, [%4];\n"
    : "=r"(r0), "=r"(r1), "=r"(r2), "=r"(r3) : "r"(addr));
}

__device__ __forceinline__ unsigned int smem_u32(const void* p) {
  return (unsigned int)__cvta_generic_to_shared(p);
}
__device__ __forceinline__ void cpa16(unsigned int dst, const void* src) {
  asm volatile("cp.async.cg.shared.global [%0], [%1], 16;\n" :: "r"(dst), "l"(src));
}
#define CP_COMMIT asm volatile("cp.async.commit_group;\n")
#define CP_WAIT0  asm volatile("cp.async.wait_group 0;\n")
#define CP_WAIT1  asm volatile("cp.async.wait_group 1;\n")

// ---------------------------------------------------------------------------
// split_all: one launch converts 4 weight matrices + 3 activations.
// Region layout (float4-granular): [4*WSZ weights][3*NACT activations]
// ---------------------------------------------------------------------------
__global__ __launch_bounds__(256) void split_all_kernel(
    const float* __restrict__ wq, const float* __restrict__ wk,
    const float* __restrict__ wv, const float* __restrict__ wo,
    const float* __restrict__ qa, const float* __restrict__ ka,
    const float* __restrict__ va,
    __nv_bfloat16* __restrict__ wh, __nv_bfloat16* __restrict__ wl,
    __nv_bfloat16* __restrict__ ah, __nv_bfloat16* __restrict__ al,
    __nv_bfloat16* __restrict__ bh, __nv_bfloat16* __restrict__ bl,
    __nv_bfloat16* __restrict__ chp, __nv_bfloat16* __restrict__ cl)
{
  size_t i = ((size_t)blockIdx.x*256 + threadIdx.x) * 4;
  const float* src;
  __nv_bfloat16 *dh, *dl;
  size_t off;
  if (i < 4*(size_t)WSZ) {
    int w = (int)(i / WSZ);
    off = i - (size_t)w*WSZ;
    src = (w == 0) ? wq : (w == 1) ? wk : (w == 2) ? wv : wo;
    dh = wh + (size_t)w*WSZ; dl = wl + (size_t)w*WSZ;
  } else {
    size_t j = i - 4*(size_t)WSZ;
    if (j >= 3*(size_t)NACT) return;
    int a = (int)(j / NACT);
    off = j - (size_t)a*NACT;
    src = (a == 0) ? qa : (a == 1) ? ka : va;
    dh = (a == 0) ? ah : (a == 1) ? bh : chp;
    dl = (a == 0) ? al : (a == 1) ? bl : cl;
  }
  float4 v = *(const float4*)(src + off);
  split4(v, dh, dl, (int)off);
}

// ---------------------------------------------------------------------------
// linear_bf16: pre-split operands, cp.async double-buffer, 1 barrier/chunk.
// attn normalization interleaved INTO the mainloop (final projection only) so
// the DRAM-bound sweep hides under tensor work.
// ---------------------------------------------------------------------------
#define LB_LD 40
#define LB_XB(buf,hl) ((buf)*30720 + (hl)*10240)
#define LB_WB(buf,hl) ((buf)*30720 + 20480 + (hl)*5120)
#define LB_CLD 68
#define LB_SMEM 61440

__global__ __launch_bounds__(256, 3) void linear_bf16_kernel(
    const __nv_bfloat16* __restrict__ Xh_g, const __nv_bfloat16* __restrict__ Xl_g,
    const __nv_bfloat16* __restrict__ Wh_g, const __nv_bfloat16* __restrict__ Wl_g,
    const float* __restrict__ bias, float* __restrict__ Out,
    __nv_bfloat16* __restrict__ OutH, __nv_bfloat16* __restrict__ OutL,
    int M, int N, int K, int mode,
    float* __restrict__ attn_n, const float* __restrict__ inv_all)
{
  extern __shared__ char sm[];
  float* Cs = (float*)sm;

  const int m0 = blockIdx.y * 128;
  const int n0 = blockIdx.x * 64;
  const int t  = threadIdx.x;
  const int wid = t >> 5;
  const int wm  = wid >> 1;
  const int wn  = wid & 1;

  {
#pragma unroll
    for (int hl = 0; hl < 2; hl++) {
      const __nv_bfloat16* Xs = hl ? Xl_g : Xh_g;
      unsigned int xb = smem_u32(sm + LB_XB(0,hl));
#pragma unroll
      for (int i = 0; i < 2; i++) {
        int seg = t + 256*i;
        int r = seg >> 2, cs = seg & 3;
        cpa16(xb + r*80 + cs*16, Xs + (size_t)(m0 + r)*K + cs*8);
      }
      const __nv_bfloat16* Ws = hl ? Wl_g : Wh_g;
      unsigned int wb = smem_u32(sm + LB_WB(0,hl));
      {
        int r = t >> 2, cs = t & 3;
        cpa16(wb + r*80 + cs*16, Ws + (size_t)(n0 + r)*K + cs*8);
      }
    }
    CP_COMMIT;
  }

  FragC c[2][2];
#pragma unroll
  for (int i = 0; i < 2; i++)
#pragma unroll
    for (int j = 0; j < 2; j++) wmma::fill_fragment(c[i][j], 0.0f);

  const int NCH = K / 32;
  const int cta = blockIdx.y * gridDim.x + blockIdx.x;
  int buf = 0;
  for (int ch = 0; ch < NCH; ch++) {
    CP_WAIT0;
    __syncthreads();
    if (ch + 1 < NCH) {
      int k0 = (ch + 1) * 32;
      int nb = buf ^ 1;
#pragma unroll
      for (int hl = 0; hl < 2; hl++) {
        const __nv_bfloat16* Xs = hl ? Xl_g : Xh_g;
        unsigned int xb = smem_u32(sm + LB_XB(nb,hl));
#pragma unroll
        for (int i = 0; i < 2; i++) {
          int seg = t + 256*i;
          int r = seg >> 2, cs = seg & 3;
          cpa16(xb + r*80 + cs*16, Xs + (size_t)(m0 + r)*K + k0 + cs*8);
        }
        const __nv_bfloat16* Ws = hl ? Wl_g : Wh_g;
        unsigned int wb = smem_u32(sm + LB_WB(nb,hl));
        {
          int r = t >> 2, cs = t & 3;
          cpa16(wb + r*80 + cs*16, Ws + (size_t)(n0 + r)*K + k0 + cs*8);
        }
      }
      CP_COMMIT;
    }
    // ---- interleaved attn-normalization slice (final projection only) ----
    if (attn_n) {
      int r0 = (ch * 128) / NCH;
      int r1 = ((ch + 1) * 128) / NCH;
      for (int rr = r0; rr < r1; rr++) {
        int row = cta * 128 + rr;
        float inv = inv_all[row];
        float* p = attn_n + (size_t)row * NS;
#pragma unroll
        for (int i2 = 0; i2 < 2; i2++) {
          int idx = (t + 256*i2) << 2;
          float4 vv = *(const float4*)(p + idx);
          vv.x *= inv; vv.y *= inv; vv.z *= inv; vv.w *= inv;
          *(float4*)(p + idx) = vv;
        }
      }
    }
    const __nv_bfloat16* Xh = (const __nv_bfloat16*)(sm + LB_XB(buf,0));
    const __nv_bfloat16* Xl = (const __nv_bfloat16*)(sm + LB_XB(buf,1));
    const __nv_bfloat16* Wh = (const __nv_bfloat16*)(sm + LB_WB(buf,0));
    const __nv_bfloat16* Wl = (const __nv_bfloat16*)(sm + LB_WB(buf,1));
#pragma unroll
    for (int ks = 0; ks < 32; ks += 16) {
      FragA ah[2], al[2];
      FragB bh[2], bl[2];
#pragma unroll
      for (int i = 0; i < 2; i++) {
        wmma::load_matrix_sync(ah[i], Xh + (wm*32 + i*16)*LB_LD + ks, LB_LD);
        wmma::load_matrix_sync(al[i], Xl + (wm*32 + i*16)*LB_LD + ks, LB_LD);
      }
#pragma unroll
      for (int j = 0; j < 2; j++) {
        wmma::load_matrix_sync(bh[j], Wh + (wn*32 + j*16)*LB_LD + ks, LB_LD);
        wmma::load_matrix_sync(bl[j], Wl + (wn*32 + j*16)*LB_LD + ks, LB_LD);
      }
#pragma unroll
      for (int i = 0; i < 2; i++)
#pragma unroll
        for (int j = 0; j < 2; j++) mma3(c[i][j], ah[i], al[i], bh[j], bl[j]);
    }
    buf ^= 1;
  }
  __syncthreads();
#pragma unroll
  for (int i = 0; i < 2; i++)
#pragma unroll
    for (int j = 0; j < 2; j++)
      wmma::store_matrix_sync(Cs + (wm*32 + i*16)*LB_CLD + wn*32 + j*16,
                              c[i][j], LB_CLD, wmma::mem_row_major);
  __syncthreads();

  if (mode == 0) {
    for (int i = t; i < 128*16; i += 256) {
      int row = i >> 4;
      int c4  = (i & 15) << 2;
      float4 v = *(const float4*)&Cs[row*LB_CLD + c4];
      float4 bb = *(const float4*)(bias + n0 + c4);
      v.x += bb.x; v.y += bb.y; v.z += bb.z; v.w += bb.w;
      *(float4*)&Out[(size_t)(m0 + row)*N + n0 + c4] = v;
    }
  } else if (mode == 1) {
    for (int i = t; i < 128*16; i += 256) {
      int row = i >> 4;
      int c4  = (i & 15) << 2;
      float4 v = *(const float4*)&Cs[row*LB_CLD + c4];
      float4 bb = *(const float4*)(bias + n0 + c4);
      v.x += bb.x; v.y += bb.y; v.z += bb.z; v.w += bb.w;
      size_t base = (size_t)(m0 + row)*N + n0 + c4;
      split4(v, OutH + base, OutL + base, 0);
    }
  } else {
    for (int j = t; j < 64*128; j += 256) {
      int d   = j >> 7;
      int row = j & 127;
      float val = Cs[row*LB_CLD + d] + bias[n0 + d];
      __nv_bfloat16 h, l;
      split1(val, h, l);
      int m  = m0 + row;
      int bb = m >> 11;
      int s  = m & 2047;
      int n  = n0 + d;
      int hh = n >> 6;
      int dd = n & 63;
      size_t idx = ((size_t)(bb*NH + hh)*NDK + dd)*NS + s;
      OutH[idx] = h;
      OutL[idx] = l;
    }
  }
}

// ---------------------------------------------------------------------------
// Fused attention: CTA = 64 q x one (b,h), chunks of 64 keys.
// QK mma (LDSM) -> exp in regs -> STG unnorm P + row sums -> PV mma from
// registers vs double-buffered V. Tail: pair-reduce + scale -> split X write;
// inv written to global (normalization happens in the final linear mainloop).
// ---------------------------------------------------------------------------
#define FLD 72
#define F_QHO 0
#define F_QLO 9216
#define F_KB(buf,hl) (18432 + (buf)*18432 + (hl)*9216)
#define F_VB(buf,hl) (55296 + (buf)*18432 + (hl)*9216)
#define F_SUMO 92160
#define F_INVO 92416
#define F_SCR  18432              // reduction scratch aliases K ring
#define F_SMEM 92672

__global__ __launch_bounds__(256, 2) void attn_fused_kernel(
    const __nv_bfloat16* __restrict__ Qh_g, const __nv_bfloat16* __restrict__ Ql_g,
    const __nv_bfloat16* __restrict__ Kh_g, const __nv_bfloat16* __restrict__ Kl_g,
    const __nv_bfloat16* __restrict__ Vth_g, const __nv_bfloat16* __restrict__ Vtl_g,
    float* __restrict__ attn_out, float* __restrict__ inv_out,
    __nv_bfloat16* __restrict__ XhG, __nv_bfloat16* __restrict__ XlG)
{
  extern __shared__ char sm[];
  float* ssum = (float*)(sm + F_SUMO);
  float* sinv = (float*)(sm + F_INVO);

  const int t  = threadIdx.x;
  const int q0 = blockIdx.x * 64;
  const int bh = blockIdx.y;
  const int b  = bh / NH, h = bh % NH;
  const int wid = t >> 5;
  const int lane = t & 31;
  const int g  = lane >> 2;
  const int tq = lane & 3;
  const int wq = (wid >> 1) * 16;
  const int wk = (wid & 1) * 32;

  const int sub = lane >> 3, l7 = lane & 7;
  const unsigned qh_addr0 = smem_u32(sm + F_QHO) +
      (unsigned)(((wq + (sub & 1)*8 + l7)*FLD + (sub >> 1)*8) * 2);
  const unsigned ql_addr0 = qh_addr0 + (F_QLO - F_QHO);
  const unsigned k_off0 = (unsigned)(((wk + (sub >> 1)*8 + l7)*FLD + (sub & 1)*8) * 2);
  const unsigned k_off1 = k_off0 + 16*FLD*2;

  const size_t qkoff = ((size_t)b*NS)*ND + h*NDK;
  const size_t voff  = (size_t)bh*NDK*NS;
  float* Arows = attn_out + ((size_t)bh*NS + q0)*NS;

  if (t < 64) ssum[t] = 0.f;

  {
    unsigned int qh = smem_u32(sm + F_QHO), ql = smem_u32(sm + F_QLO);
#pragma unroll
    for (int i = 0; i < 2; i++) {
      int f = t + 256*i;
      int r = f >> 3;
      int c = (f & 7) * 8;
      cpa16(qh + r*144 + c*2, Qh_g + qkoff + (size_t)(q0 + r)*ND + c);
      cpa16(ql + r*144 + c*2, Ql_g + qkoff + (size_t)(q0 + r)*ND + c);
    }
    unsigned int kh = smem_u32(sm + F_KB(0,0)), kl = smem_u32(sm + F_KB(0,1));
    unsigned int vh = smem_u32(sm + F_VB(0,0)), vl = smem_u32(sm + F_VB(0,1));
#pragma unroll
    for (int i = 0; i < 2; i++) {
      int f = t + 256*i;
      int r = f >> 3;
      int c = (f & 7) * 8;
      cpa16(kh + r*144 + c*2, Kh_g + qkoff + (size_t)r*ND + c);
      cpa16(kl + r*144 + c*2, Kl_g + qkoff + (size_t)r*ND + c);
      cpa16(vh + r*144 + c*2, Vth_g + voff + (size_t)r*NS + c);
      cpa16(vl + r*144 + c*2, Vtl_g + voff + (size_t)r*NS + c);
    }
    CP_COMMIT;
  }

  float o[8][4];
#pragma unroll
  for (int dt = 0; dt < 8; dt++)
#pragma unroll
    for (int j = 0; j < 4; j++) o[dt][j] = 0.f;

  int buf = 0;
  for (int ch = 0; ch < 32; ch++) {
    if (ch < 31) {
      int kt = (ch + 1) * 64;
      int nb = buf ^ 1;
      unsigned int kh = smem_u32(sm + F_KB(nb,0)), kl = smem_u32(sm + F_KB(nb,1));
      unsigned int vh = smem_u32(sm + F_VB(nb,0)), vl = smem_u32(sm + F_VB(nb,1));
#pragma unroll
      for (int i = 0; i < 2; i++) {
        int f = t + 256*i;
        int r = f >> 3;
        int c = (f & 7) * 8;
        cpa16(kh + r*144 + c*2, Kh_g + qkoff + (size_t)(kt + r)*ND + c);
        cpa16(kl + r*144 + c*2, Kl_g + qkoff + (size_t)(kt + r)*ND + c);
        cpa16(vh + r*144 + c*2, Vth_g + voff + (size_t)r*NS + kt + c);
        cpa16(vl + r*144 + c*2, Vtl_g + voff + (size_t)r*NS + kt + c);
      }
      CP_COMMIT;
      CP_WAIT1;
    } else {
      CP_WAIT0;
    }
    __syncthreads();

    // ---- QK ----
    const unsigned kh_base = smem_u32(sm + F_KB(buf, 0));
    const unsigned kl_base = kh_base + 9216;

    float c[4][4];
#pragma unroll
    for (int nt = 0; nt < 4; nt++)
#pragma unroll
      for (int j = 0; j < 4; j++) c[nt][j] = 0.f;

#pragma unroll
    for (int ks = 0; ks < 64; ks += 16) {
      unsigned ah[4], al[4];
      ldsm_x4(ah[0], ah[1], ah[2], ah[3], qh_addr0 + ks*2);
      ldsm_x4(al[0], al[1], al[2], al[3], ql_addr0 + ks*2);
      unsigned bh00, bh01, bh10, bh11, bh20, bh21, bh30, bh31;
      unsigned bl00, bl01, bl10, bl11, bl20, bl21, bl30, bl31;
      ldsm_x4(bh00, bh01, bh10, bh11, kh_base + k_off0 + ks*2);
      ldsm_x4(bh20, bh21, bh30, bh31, kh_base + k_off1 + ks*2);
      ldsm_x4(bl00, bl01, bl10, bl11, kl_base + k_off0 + ks*2);
      ldsm_x4(bl20, bl21, bl30, bl31, kl_base + k_off1 + ks*2);
      mma16816(c[0], ah, bh00, bh01);
      mma16816(c[0], ah, bl00, bl01);
      mma16816(c[0], al, bh00, bh01);
      mma16816(c[1], ah, bh10, bh11);
      mma16816(c[1], ah, bl10, bl11);
      mma16816(c[1], al, bh10, bh11);
      mma16816(c[2], ah, bh20, bh21);
      mma16816(c[2], ah, bl20, bl21);
      mma16816(c[2], al, bh20, bh21);
      mma16816(c[3], ah, bh30, bh31);
      mma16816(c[3], ah, bl30, bl31);
      mma16816(c[3], al, bh30, bh31);
    }

    // ---- exp + sums + STG of unnormalized P ----
    float ee[4][4];
    float s0 = 0.f, s1 = 0.f;
    const int r0 = wq + g, r1 = wq + g + 8;
#pragma unroll
    for (int nt = 0; nt < 4; nt++) {
      int gcol = ch*64 + wk + nt*8 + tq*2;
      float e0 = __expf(c[nt][0] * 0.125f);
      float e1 = __expf(c[nt][1] * 0.125f);
      float e2 = __expf(c[nt][2] * 0.125f);
      float e3 = __expf(c[nt][3] * 0.125f);
      ee[nt][0] = e0; ee[nt][1] = e1; ee[nt][2] = e2; ee[nt][3] = e3;
      s0 += e0 + e1;
      s1 += e2 + e3;
      float2 p0; p0.x = e0; p0.y = e1;
      float2 p1; p1.x = e2; p1.y = e3;
      *(float2*)&Arows[(size_t)r0*NS + gcol] = p0;
      *(float2*)&Arows[(size_t)r1*NS + gcol] = p1;
    }
    s0 += __shfl_xor_sync(0xffffffffu, s0, 1);
    s0 += __shfl_xor_sync(0xffffffffu, s0, 2);
    s1 += __shfl_xor_sync(0xffffffffu, s1, 1);
    s1 += __shfl_xor_sync(0xffffffffu, s1, 2);
    if (tq == 0) {
      atomicAdd(&ssum[r0], s0);
      atomicAdd(&ssum[r1], s1);
    }

    // ---- PV: feed exp straight from registers ----
    const __nv_bfloat16* Vbh = (const __nv_bfloat16*)(sm + F_VB(buf, 0));
    const __nv_bfloat16* Vbl = (const __nv_bfloat16*)(sm + F_VB(buf, 1));
#pragma unroll
    for (int kt2 = 0; kt2 < 2; kt2++) {
      unsigned ap_h[4], ap_l[4];
      const int n0t = kt2*2;
      pack_hilo(ee[n0t  ][0], ee[n0t  ][1], ap_h[0], ap_l[0]);
      pack_hilo(ee[n0t  ][2], ee[n0t  ][3], ap_h[1], ap_l[1]);
      pack_hilo(ee[n0t+1][0], ee[n0t+1][1], ap_h[2], ap_l[2]);
      pack_hilo(ee[n0t+1][2], ee[n0t+1][3], ap_h[3], ap_l[3]);
      const int kkk = wk + kt2*16;
#pragma unroll
      for (int dt = 0; dt < 8; dt++) {
        const int vrow = dt*8 + g;
        unsigned b0h = *(const unsigned*)&Vbh[vrow*FLD + kkk + tq*2];
        unsigned b1h = *(const unsigned*)&Vbh[vrow*FLD + kkk + 8 + tq*2];
        unsigned b0l = *(const unsigned*)&Vbl[vrow*FLD + kkk + tq*2];
        unsigned b1l = *(const unsigned*)&Vbl[vrow*FLD + kkk + 8 + tq*2];
        mma16816(o[dt], ap_h, b0h, b1h);
        mma16816(o[dt], ap_l, b0h, b1h);
        mma16816(o[dt], ap_h, b0l, b1l);
      }
    }
    __syncthreads();
    buf ^= 1;
  }

  // ---- inv ----
  if (t < 64) {
    float iv = 1.0f / ssum[t];
    sinv[t] = iv;
    inv_out[(size_t)bh*NS + q0 + t] = iv;
  }
  __syncthreads();

  // ---- cross-warp pair reduction (wk=32 warp dumps to scratch) ----
  float* scr = (float*)(sm + F_SCR);   // [wq/16][16 rows][68 stride]
  const int scrb = (wid >> 1) * 16 * 68;
  if (wid & 1) {
#pragma unroll
    for (int dt = 0; dt < 8; dt++) {
      scr[scrb + (g    )*68 + dt*8 + tq*2    ] = o[dt][0];
      scr[scrb + (g    )*68 + dt*8 + tq*2 + 1] = o[dt][1];
      scr[scrb + (g + 8)*68 + dt*8 + tq*2    ] = o[dt][2];
      scr[scrb + (g + 8)*68 + dt*8 + tq*2 + 1] = o[dt][3];
    }
  }
  __syncthreads();
  if ((wid & 1) == 0) {
    const float inv0 = sinv[wq + g];
    const float inv1 = sinv[wq + g + 8];
    const size_t xb0 = (size_t)(b*NS + q0 + wq + g    )*ND + h*NDK;
    const size_t xb1 = (size_t)(b*NS + q0 + wq + g + 8)*ND + h*NDK;
#pragma unroll
    for (int dt = 0; dt < 8; dt++) {
      int d0 = dt*8 + tq*2;
      float v00 = (o[dt][0] + scr[scrb + (g    )*68 + d0    ]) * inv0;
      float v01 = (o[dt][1] + scr[scrb + (g    )*68 + d0 + 1]) * inv0;
      float v10 = (o[dt][2] + scr[scrb + (g + 8)*68 + d0    ]) * inv1;
      float v11 = (o[dt][3] + scr[scrb + (g + 8)*68 + d0 + 1]) * inv1;
      unsigned h0, l0, h1, l1;
      pack_hilo(v00, v01, h0, l0);
      pack_hilo(v10, v11, h1, l1);
      *(unsigned*)&XhG[xb0 + d0] = h0;
      *(unsigned*)&XlG[xb0 + d0] = l0;
      *(unsigned*)&XhG[xb1 + d0] = h1;
      *(unsigned*)&XlG[xb1 + d0] = l1;
    }
  }
}

// ---------------------------------------------------------------------------
extern "C" void kernel_launch(void* const* d_in, const int* in_sizes, int n_in,
                              void* d_out, int out_size)
{
  const float* q   = (const float*)d_in[0];
  const float* k   = (const float*)d_in[1];
  const float* v   = (const float*)d_in[2];
  const float* w_q = (const float*)d_in[3];
  const float* b_q = (const float*)d_in[4];
  const float* w_k = (const float*)d_in[5];
  const float* b_k = (const float*)d_in[6];
  const float* w_v = (const float*)d_in[7];
  const float* b_v = (const float*)d_in[8];
  const float* w_o = (const float*)d_in[9];
  const float* b_o = (const float*)d_in[10];

  __nv_bfloat16 *qh, *ql, *kh, *kl, *vth, *vtl;
  __nv_bfloat16 *ah, *al, *bh2, *bl2, *ch2, *cl2, *xh, *xl, *wh, *wl;
  float *ginv;
  cudaGetSymbolAddress((void**)&qh,  g_Qh);
  cudaGetSymbolAddress((void**)&ql,  g_Ql);
  cudaGetSymbolAddress((void**)&kh,  g_Kh);
  cudaGetSymbolAddress((void**)&kl,  g_Kl);
  cudaGetSymbolAddress((void**)&vth, g_Vth);
  cudaGetSymbolAddress((void**)&vtl, g_Vtl);
  cudaGetSymbolAddress((void**)&ah,  g_Ah);
  cudaGetSymbolAddress((void**)&al,  g_Al);
  cudaGetSymbolAddress((void**)&bh2, g_Bh);
  cudaGetSymbolAddress((void**)&bl2, g_Bl);
  cudaGetSymbolAddress((void**)&ch2, g_Ch);
  cudaGetSymbolAddress((void**)&cl2, g_Cl);
  cudaGetSymbolAddress((void**)&xh,  g_Xh);
  cudaGetSymbolAddress((void**)&xl,  g_Xl);
  cudaGetSymbolAddress((void**)&wh,  g_Wh);
  cudaGetSymbolAddress((void**)&wl,  g_Wl);
  cudaGetSymbolAddress((void**)&ginv, g_inv);

  const size_t OUT_E = (size_t)NB * NS * ND;
  float* outp  = (float*)d_out;
  float* attnp = outp + OUT_E;

  cudaFuncSetAttribute(linear_bf16_kernel, cudaFuncAttributeMaxDynamicSharedMemorySize, LB_SMEM);
  cudaFuncSetAttribute(attn_fused_kernel,  cudaFuncAttributeMaxDynamicSharedMemorySize, F_SMEM);

  // one split launch for everything
  const size_t TOTAL4 = (4*(size_t)WSZ + 3*(size_t)NACT) / 4;   // 2,949,120
  const int GSPLIT = (int)((TOTAL4 + 255) / 256);
  split_all_kernel<<<GSPLIT, 256>>>(w_q, w_k, w_v, w_o, q, k, v,
                                    wh, wl, ah, al, bh2, bl2, ch2, cl2);

  dim3 gproj(ND/64, NM/128);   // (12, 32)
  linear_bf16_kernel<<<gproj, 256, LB_SMEM>>>(ah, al, wh + 0*WSZ, wl + 0*WSZ,
      b_q, nullptr, qh, ql, NM, ND, ND, 1, nullptr, nullptr);
  linear_bf16_kernel<<<gproj, 256, LB_SMEM>>>(bh2, bl2, wh + 1*WSZ, wl + 1*WSZ,
      b_k, nullptr, kh, kl, NM, ND, ND, 1, nullptr, nullptr);
  linear_bf16_kernel<<<gproj, 256, LB_SMEM>>>(ch2, cl2, wh + 2*WSZ, wl + 2*WSZ,
      b_v, nullptr, vth, vtl, NM, ND, ND, 2, nullptr, nullptr);

  dim3 gattn(NS/64, NB*NH);    // (32, 24)
  attn_fused_kernel<<<gattn, 256, F_SMEM>>>(qh, ql, kh, kl, vth, vtl, attnp, ginv, xh, xl);

  // final projection with attn normalization interleaved into the mainloop
  linear_bf16_kernel<<<gproj, 256, LB_SMEM>>>(xh, xl, wh + 3*WSZ, wl + 3*WSZ,
      b_o, outp, nullptr, nullptr, NM, ND, ND, 0, attnp, ginv);
}